// round 10
// baseline (speedup 1.0000x reference)
#include <cuda_runtime.h>
#include <cuda_fp16.h>
#include <cstdint>
#include <cstddef>

#define NN 50000
#define EE 800000
#define FIN 256
#define HID 128
#define HEADS 4
#define NGRAPH 50
#define NEG_SLOPE 0.2f

// ---------------- scratch (device globals; no allocation allowed) -------------
__device__ __half g_hh[(size_t)NN * HEADS * HID];    // GEMM output (fp16 messages)
__device__ __half g_acth[(size_t)NN * HEADS * HID];  // activations (fp16), layer input
__device__ __half g_xh[(size_t)NN * FIN];            // x converted to fp16
__device__ __half g_wh[512 * 512 + 256 * 512 + 512 * 128]; // fp16 weights
__device__ float g_alpha[2 * NN * HEADS];            // [0]=as, [NN*HEADS]=ad
__device__ int   g_deg[NN];
__device__ int   g_rowstart[NN + 1];
__device__ int   g_cursor[NN];
__device__ int   g_csr_src[EE];
__device__ float g_pool[NGRAPH * HID];
__device__ float g_cnt[NGRAPH];

// ==================== fp32 -> fp16 conversion ====================
__global__ void f2h_kernel(const float* __restrict__ in, __half* __restrict__ out, int n4)
{
    int i = blockIdx.x * blockDim.x + threadIdx.x;
    if (i >= n4) return;
    float4 v = ((const float4*)in)[i];
    __half2 a = __float22half2_rn(make_float2(v.x, v.y));
    __half2 b = __float22half2_rn(make_float2(v.z, v.w));
    ((__half2*)out)[2 * i + 0] = a;
    ((__half2*)out)[2 * i + 1] = b;
}

// ==================== fp16 tensor-core GEMM + fused alpha epilogue ====================
// C[M,N] = A[M,K] @ B[K,N]; A,B,C fp16, fp32 accumulate. Each 128-col block tile
// covers one head; per-row alpha dots reduced across n-warps in smem, plain store.
// Block tile 128x128, BK=64, 256 threads = 8 warps (2m x 4n), warp tile 64x32.
__global__ __launch_bounds__(256) void h16_gemm_alpha_kernel(
    const __half* __restrict__ A, const __half* __restrict__ B, __half* __restrict__ C,
    int M, int K, int N,
    const float* __restrict__ a_src, const float* __restrict__ a_dst,  // [H][HID]
    float* __restrict__ as_out, float* __restrict__ ad_out, int H)
{
    __shared__ __align__(16) __half As[128][72];   // [m][k], pitch 72 halfs (144B)
    __shared__ __align__(16) __half Bs[128][72];   // TRANSPOSED: [n][k]

    const int tid  = threadIdx.x;
    const int lane = tid & 31;
    const int warp = tid >> 5;
    const int wm = (warp & 1) * 64;
    const int wn = (warp >> 1) * 32;
    const int wnIdx = warp >> 1;

    const int mBase = blockIdx.y * 128;
    const int nBase = blockIdx.x * 128;

    float c[4][4][4];
#pragma unroll
    for (int mi = 0; mi < 4; mi++)
#pragma unroll
        for (int ni = 0; ni < 4; ni++)
#pragma unroll
            for (int q = 0; q < 4; q++) c[mi][ni][q] = 0.f;

    const int g = lane >> 2;
    const int l = lane & 3;

    for (int k0 = 0; k0 < K; k0 += 64) {
        // ---- load A tile: 128 rows x 64 halfs, uint4 (8 halfs) per op ----
#pragma unroll
        for (int p = 0; p < 4; p++) {
            int idx = tid + p * 256;          // 0..1023
            int row = idx >> 3;               // 8 uint4 per row
            int col = (idx & 7) * 8;
            uint4 v = make_uint4(0u, 0u, 0u, 0u);
            if (mBase + row < M)
                v = *(const uint4*)&A[(size_t)(mBase + row) * K + k0 + col];
            *(uint4*)&As[row][col] = v;
        }
        // ---- load B tile transposed: global [k][n] -> Bs[n][k] ----
#pragma unroll
        for (int p = 0; p < 4; p++) {
            int idx = tid + p * 256;          // 0..1023
            int k = idx >> 4;                 // 16 uint4 per k-row
            int n8 = (idx & 15) * 8;
            uint4 v = *(const uint4*)&B[(size_t)(k0 + k) * N + nBase + n8];
            const __half* hv = (const __half*)&v;
#pragma unroll
            for (int i = 0; i < 8; i++) Bs[n8 + i][k] = hv[i];
        }
        __syncthreads();

#pragma unroll
        for (int kk = 0; kk < 64; kk += 16) {
            uint32_t a[4][4], b[4][2];
            const int kh = kk >> 1;           // half2 index base
#pragma unroll
            for (int mi = 0; mi < 4; mi++) {
                int r = wm + mi * 16 + g;
                const uint32_t* r0 = (const uint32_t*)&As[r][0];
                const uint32_t* r1 = (const uint32_t*)&As[r + 8][0];
                a[mi][0] = r0[kh + l];
                a[mi][1] = r1[kh + l];
                a[mi][2] = r0[kh + l + 4];
                a[mi][3] = r1[kh + l + 4];
            }
#pragma unroll
            for (int ni = 0; ni < 4; ni++) {
                int n = wn + ni * 8 + g;
                const uint32_t* rn = (const uint32_t*)&Bs[n][0];
                b[ni][0] = rn[kh + l];
                b[ni][1] = rn[kh + l + 4];
            }
#pragma unroll
            for (int mi = 0; mi < 4; mi++)
#pragma unroll
                for (int ni = 0; ni < 4; ni++) {
                    asm volatile(
                        "mma.sync.aligned.m16n8k16.row.col.f32.f16.f16.f32 "
                        "{%0,%1,%2,%3}, {%4,%5,%6,%7}, {%8,%9}, {%0,%1,%2,%3};\n"
                        : "+f"(c[mi][ni][0]), "+f"(c[mi][ni][1]),
                          "+f"(c[mi][ni][2]), "+f"(c[mi][ni][3])
                        : "r"(a[mi][0]), "r"(a[mi][1]), "r"(a[mi][2]), "r"(a[mi][3]),
                          "r"(b[ni][0]), "r"(b[ni][1]));
                }
        }
        __syncthreads();
    }

    const int hh = nBase / HID;   // head owned by this block column

    // repurpose As smem for the alpha reduction: [128 rows][4 wn][2 (s,d)] floats
    float* s_red = (float*)&As[0][0];

#pragma unroll
    for (int mi = 0; mi < 4; mi++) {
        int r0 = mBase + wm + mi * 16 + g;
        int r1 = r0 + 8;
        float ps0 = 0.f, pd0 = 0.f, ps1 = 0.f, pd1 = 0.f;
#pragma unroll
        for (int ni = 0; ni < 4; ni++) {
            int col = nBase + wn + ni * 8 + 2 * l;
            if (r0 < M)
                *(__half2*)&C[(size_t)r0 * N + col] =
                    __float22half2_rn(make_float2(c[mi][ni][0], c[mi][ni][1]));
            if (r1 < M)
                *(__half2*)&C[(size_t)r1 * N + col] =
                    __float22half2_rn(make_float2(c[mi][ni][2], c[mi][ni][3]));
            int cc = wn + ni * 8 + 2 * l;
            float sa0 = a_src[hh * HID + cc],     sa1 = a_src[hh * HID + cc + 1];
            float da0 = a_dst[hh * HID + cc],     da1 = a_dst[hh * HID + cc + 1];
            ps0 += c[mi][ni][0] * sa0 + c[mi][ni][1] * sa1;
            pd0 += c[mi][ni][0] * da0 + c[mi][ni][1] * da1;
            ps1 += c[mi][ni][2] * sa0 + c[mi][ni][3] * sa1;
            pd1 += c[mi][ni][2] * da0 + c[mi][ni][3] * da1;
        }
#pragma unroll
        for (int o = 1; o <= 2; o <<= 1) {
            ps0 += __shfl_xor_sync(0xffffffffu, ps0, o);
            pd0 += __shfl_xor_sync(0xffffffffu, pd0, o);
            ps1 += __shfl_xor_sync(0xffffffffu, ps1, o);
            pd1 += __shfl_xor_sync(0xffffffffu, pd1, o);
        }
        if (l == 0) {
            int lr0 = wm + mi * 16 + g;
            s_red[(lr0)     * 8 + wnIdx * 2 + 0] = ps0;
            s_red[(lr0)     * 8 + wnIdx * 2 + 1] = pd0;
            s_red[(lr0 + 8) * 8 + wnIdx * 2 + 0] = ps1;
            s_red[(lr0 + 8) * 8 + wnIdx * 2 + 1] = pd1;
        }
    }
    __syncthreads();
    if (tid < 128) {
        int gr = mBase + tid;
        if (gr < M) {
            float as = s_red[tid * 8 + 0] + s_red[tid * 8 + 2] +
                       s_red[tid * 8 + 4] + s_red[tid * 8 + 6];
            float ad = s_red[tid * 8 + 1] + s_red[tid * 8 + 3] +
                       s_red[tid * 8 + 5] + s_red[tid * 8 + 7];
            as_out[gr * H + hh] = as;
            ad_out[gr * H + hh] = ad;
        }
    }
}

// ==================== CSR build ====================
__global__ void deg_kernel(const int* __restrict__ dst, int* __restrict__ deg, int E)
{
    int e = blockIdx.x * blockDim.x + threadIdx.x;
    if (e < E) atomicAdd(&deg[dst[e]], 1);
}

__global__ __launch_bounds__(1024) void scan_kernel(const int* __restrict__ deg,
                                                    int* __restrict__ rowstart, int n)
{
    __shared__ int warp_sums[32];
    __shared__ int s_carry;
    int t = threadIdx.x;
    int lane = t & 31, w = t >> 5;
    if (t == 0) s_carry = 0;
    __syncthreads();
    for (int base = 0; base < n; base += 1024) {
        int i = base + t;
        int x = (i < n) ? deg[i] : 0;
        int v = x;
#pragma unroll
        for (int o = 1; o < 32; o <<= 1) {
            int y = __shfl_up_sync(0xffffffffu, v, o);
            if (lane >= o) v += y;
        }
        if (lane == 31) warp_sums[w] = v;
        __syncthreads();
        if (w == 0) {
            int s = warp_sums[lane];
#pragma unroll
            for (int o = 1; o < 32; o <<= 1) {
                int y = __shfl_up_sync(0xffffffffu, s, o);
                if (lane >= o) s += y;
            }
            warp_sums[lane] = s;
        }
        __syncthreads();
        int prefix = s_carry + (w > 0 ? warp_sums[w - 1] : 0) + v - x;
        if (i < n) rowstart[i] = prefix;
        __syncthreads();
        if (t == 0) s_carry += warp_sums[31];
        __syncthreads();
    }
    if (t == 0) rowstart[n] = s_carry;
}

__global__ void csr_scatter_kernel(const int* __restrict__ src, const int* __restrict__ dst,
                                   int* __restrict__ cursor, int* __restrict__ csr_src, int E)
{
    int e = blockIdx.x * blockDim.x + threadIdx.x;
    if (e >= E) return;
    int p = atomicAdd(&cursor[dst[e]], 1);
    csr_src[p] = src[e];
}

// ==================== FUSED softmax + aggregate + bias + ELU (warp per node) ====================
// OUTH=1: store fp16 (next-layer activations). OUTH=0: store fp32 (final output).
template <int H, int OUTH>
__global__ __launch_bounds__(256) void gat_fused_kernel(
    const int* __restrict__ rowstart, const int* __restrict__ csr_src,
    const float* __restrict__ as_, const float* __restrict__ ad_,
    const __half* __restrict__ hbuf, const float* __restrict__ bias,
    void* __restrict__ out_, int do_elu, int n)
{
    __shared__ int   s_src[8][32];
    __shared__ float s_cf[8][32][H];

    const int w = threadIdx.x >> 5;
    const int lane = threadIdx.x & 31;
    const int d = blockIdx.x * 8 + w;
    if (d >= n) return;
    const int e0 = rowstart[d];
    const int deg = rowstart[d + 1] - e0;
    const int W = H * HID;
    const int CH = (H == 4) ? 16 : 4;
    const int c0 = lane * CH;
    const int hd = (H == 4) ? (lane >> 3) : 0;
    const float NEG_INF = -__int_as_float(0x7f800000);

    float adv[H];
#pragma unroll
    for (int h = 0; h < H; h++) adv[h] = ad_[d * H + h];

    float acc[16];
#pragma unroll
    for (int i = 0; i < CH; i++) acc[i] = 0.f;

    if (deg <= 32) {
        bool valid = lane < deg;
        int s = 0;
        float v[H];
        if (valid) {
            s = __ldg(&csr_src[e0 + lane]);
            if (H == 4) {
                float4 av = __ldg((const float4*)&as_[s * 4]);
                v[0] = av.x + adv[0]; v[1] = av.y + adv[1];
                v[2] = av.z + adv[2]; v[3] = av.w + adv[3];
            } else {
                v[0] = __ldg(&as_[s]) + adv[0];
            }
#pragma unroll
            for (int h = 0; h < H; h++) v[h] = (v[h] >= 0.f) ? v[h] : NEG_SLOPE * v[h];
        } else {
#pragma unroll
            for (int h = 0; h < H; h++) v[h] = NEG_INF;
        }
#pragma unroll
        for (int h = 0; h < H; h++) {
            float mx = v[h];
#pragma unroll
            for (int o = 16; o; o >>= 1)
                mx = fmaxf(mx, __shfl_xor_sync(0xffffffffu, mx, o));
            float e = valid ? expf(v[h] - mx) : 0.f;
            float sm = e;
#pragma unroll
            for (int o = 16; o; o >>= 1)
                sm += __shfl_xor_sync(0xffffffffu, sm, o);
            v[h] = e / (sm + 1e-16f);
        }
        s_src[w][lane] = s;
#pragma unroll
        for (int h = 0; h < H; h++) s_cf[w][lane][h] = v[h];
        __syncwarp();

#pragma unroll 4
        for (int j = 0; j < deg; j++) {
            int sj = s_src[w][j];
            float cf = s_cf[w][j][hd];
            const __half* hp = hbuf + (size_t)sj * W + c0;
            if (H == 4) {
                uint4 r0 = __ldg((const uint4*)hp);
                uint4 r1 = __ldg((const uint4*)(hp + 8));
                const __half2* p0 = (const __half2*)&r0;
                const __half2* p1 = (const __half2*)&r1;
#pragma unroll
                for (int q = 0; q < 4; q++) {
                    float2 f0 = __half22float2(p0[q]);
                    float2 f1 = __half22float2(p1[q]);
                    acc[2 * q + 0] += f0.x * cf;
                    acc[2 * q + 1] += f0.y * cf;
                    acc[8 + 2 * q + 0] += f1.x * cf;
                    acc[8 + 2 * q + 1] += f1.y * cf;
                }
            } else {
                uint2 r0 = __ldg((const uint2*)hp);
                const __half2* p0 = (const __half2*)&r0;
#pragma unroll
                for (int q = 0; q < 2; q++) {
                    float2 f0 = __half22float2(p0[q]);
                    acc[2 * q + 0] += f0.x * cf;
                    acc[2 * q + 1] += f0.y * cf;
                }
            }
        }
    } else {
        // generic path (deg > 32)
        float mx[H], sm[H];
#pragma unroll
        for (int h = 0; h < H; h++) { mx[h] = NEG_INF; sm[h] = 0.f; }
        for (int j = lane; j < deg; j += 32) {
            int s = __ldg(&csr_src[e0 + j]);
#pragma unroll
            for (int h = 0; h < H; h++) {
                float v = as_[s * H + h] + adv[h];
                v = (v >= 0.f) ? v : NEG_SLOPE * v;
                mx[h] = fmaxf(mx[h], v);
            }
        }
#pragma unroll
        for (int h = 0; h < H; h++)
#pragma unroll
            for (int o = 16; o; o >>= 1)
                mx[h] = fmaxf(mx[h], __shfl_xor_sync(0xffffffffu, mx[h], o));
        for (int j = lane; j < deg; j += 32) {
            int s = __ldg(&csr_src[e0 + j]);
#pragma unroll
            for (int h = 0; h < H; h++) {
                float v = as_[s * H + h] + adv[h];
                v = (v >= 0.f) ? v : NEG_SLOPE * v;
                sm[h] += expf(v - mx[h]);
            }
        }
        float inv[H];
#pragma unroll
        for (int h = 0; h < H; h++) {
#pragma unroll
            for (int o = 16; o; o >>= 1)
                sm[h] += __shfl_xor_sync(0xffffffffu, sm[h], o);
            inv[h] = 1.f / (sm[h] + 1e-16f);
        }

        for (int base = 0; base < deg; base += 32) {
            int j = base + lane;
            bool valid = j < deg;
            int s = 0;
            float cf[H];
            if (valid) {
                s = __ldg(&csr_src[e0 + j]);
#pragma unroll
                for (int h = 0; h < H; h++) {
                    float v = as_[s * H + h] + adv[h];
                    v = (v >= 0.f) ? v : NEG_SLOPE * v;
                    cf[h] = expf(v - mx[h]) * inv[h];
                }
            } else {
#pragma unroll
                for (int h = 0; h < H; h++) cf[h] = 0.f;
            }
            __syncwarp();
            s_src[w][lane] = s;
#pragma unroll
            for (int h = 0; h < H; h++) s_cf[w][lane][h] = cf[h];
            __syncwarp();

            int nn = min(32, deg - base);
#pragma unroll 4
            for (int jj = 0; jj < nn; jj++) {
                int sj = s_src[w][jj];
                float cc = s_cf[w][jj][hd];
                const __half* hp = hbuf + (size_t)sj * W + c0;
                if (H == 4) {
                    uint4 r0 = __ldg((const uint4*)hp);
                    uint4 r1 = __ldg((const uint4*)(hp + 8));
                    const __half2* p0 = (const __half2*)&r0;
                    const __half2* p1 = (const __half2*)&r1;
#pragma unroll
                    for (int q = 0; q < 4; q++) {
                        float2 f0 = __half22float2(p0[q]);
                        float2 f1 = __half22float2(p1[q]);
                        acc[2 * q + 0] += f0.x * cc;
                        acc[2 * q + 1] += f0.y * cc;
                        acc[8 + 2 * q + 0] += f1.x * cc;
                        acc[8 + 2 * q + 1] += f1.y * cc;
                    }
                } else {
                    uint2 r0 = __ldg((const uint2*)hp);
                    const __half2* p0 = (const __half2*)&r0;
#pragma unroll
                    for (int q = 0; q < 2; q++) {
                        float2 f0 = __half22float2(p0[q]);
                        acc[2 * q + 0] += f0.x * cc;
                        acc[2 * q + 1] += f0.y * cc;
                    }
                }
            }
        }
    }

    // epilogue: bias + optional ELU, store fp16 or fp32
    float v[16];
#pragma unroll
    for (int i = 0; i < CH; i += 4) {
        float4 b = *(const float4*)&bias[c0 + i];
        v[i + 0] = acc[i + 0] + b.x;
        v[i + 1] = acc[i + 1] + b.y;
        v[i + 2] = acc[i + 2] + b.z;
        v[i + 3] = acc[i + 3] + b.w;
    }
    if (do_elu) {
#pragma unroll
        for (int i = 0; i < CH; i++) v[i] = (v[i] > 0.f) ? v[i] : expm1f(v[i]);
    }
    if (OUTH) {
        __half* out = (__half*)out_;
        __half2 hv[8];
#pragma unroll
        for (int i = 0; i < CH / 2; i++)
            hv[i] = __float22half2_rn(make_float2(v[2 * i], v[2 * i + 1]));
        if (H == 4) {
            *(uint4*)&out[(size_t)d * W + c0]     = *(uint4*)&hv[0];
            *(uint4*)&out[(size_t)d * W + c0 + 8] = *(uint4*)&hv[4];
        } else {
            *(uint2*)&out[(size_t)d * W + c0] = *(uint2*)&hv[0];
        }
    } else {
        float* out = (float*)out_;
#pragma unroll
        for (int i = 0; i < CH; i += 4)
            *(float4*)&out[(size_t)d * W + c0 + i] =
                make_float4(v[i], v[i + 1], v[i + 2], v[i + 3]);
    }
}

// ==================== pooling ====================
__global__ void pool_sum_kernel(const float* __restrict__ node_emb, const int* __restrict__ batch,
                                float* __restrict__ pool, float* __restrict__ cnt, int n)
{
    int node = blockIdx.x;
    int t = threadIdx.x;
    int g = batch[node];
    atomicAdd(&pool[g * HID + t], node_emb[(size_t)node * HID + t]);
    if (t == 0) atomicAdd(&cnt[g], 1.0f);
}

__global__ void pool_div_kernel(const float* __restrict__ pool, const float* __restrict__ cnt,
                                float* __restrict__ out)
{
    int i = blockIdx.x * blockDim.x + threadIdx.x;
    if (i >= NGRAPH * HID) return;
    int g = i / HID;
    out[i] = pool[i] / fmaxf(cnt[g], 1.0f);
}

// ==================== host side ====================
static void run_gat_layer(const __half* inH, int fin,
                          const __half* Wh, const float* a_s, const float* a_d, const float* bias,
                          int heads, void* out, int out_half, int do_elu,
                          int n, const int* rowstart, const int* csr_src,
                          __half* hbuf, float* alphab)
{
    const int width = heads * HID;
    float* asb = alphab;
    float* adb = alphab + NN * HEADS;

    dim3 ggrid(width / 128, (n + 127) / 128);
    h16_gemm_alpha_kernel<<<ggrid, 256>>>(inH, Wh, hbuf, n, fin, width,
                                          a_s, a_d, asb, adb, heads);

    int wgrid = (n + 7) / 8;
    if (heads == 4) {
        if (out_half)
            gat_fused_kernel<4, 1><<<wgrid, 256>>>(rowstart, csr_src, asb, adb, hbuf, bias, out, do_elu, n);
        else
            gat_fused_kernel<4, 0><<<wgrid, 256>>>(rowstart, csr_src, asb, adb, hbuf, bias, out, do_elu, n);
    } else {
        gat_fused_kernel<1, 0><<<wgrid, 256>>>(rowstart, csr_src, asb, adb, hbuf, bias, out, do_elu, n);
    }
}

extern "C" void kernel_launch(void* const* d_in, const int* in_sizes, int n_in,
                              void* d_out, int out_size)
{
    const float* x     = (const float*)d_in[0];
    const int*   ei    = (const int*)d_in[1];
    const int*   batch = (const int*)d_in[2];
    const float* W1  = (const float*)d_in[3];
    const float* a1s = (const float*)d_in[4];
    const float* a1d = (const float*)d_in[5];
    const float* b1  = (const float*)d_in[6];
    const float* W2  = (const float*)d_in[7];
    const float* a2s = (const float*)d_in[8];
    const float* a2d = (const float*)d_in[9];
    const float* b2  = (const float*)d_in[10];
    const float* W3  = (const float*)d_in[11];
    const float* a3s = (const float*)d_in[12];
    const float* a3d = (const float*)d_in[13];
    const float* b3  = (const float*)d_in[14];

    const int n = in_sizes[0] / FIN;
    const int E = in_sizes[1] / 2;
    const int* src = ei;
    const int* dst = ei + E;

    float *alphab, *poolb, *cntb;
    __half *hbuf, *actH, *xH, *wH;
    int *degb, *rowstartb, *cursorb, *csrsrcb;
    cudaGetSymbolAddress((void**)&hbuf,      g_hh);
    cudaGetSymbolAddress((void**)&actH,      g_acth);
    cudaGetSymbolAddress((void**)&xH,        g_xh);
    cudaGetSymbolAddress((void**)&wH,        g_wh);
    cudaGetSymbolAddress((void**)&alphab,    g_alpha);
    cudaGetSymbolAddress((void**)&degb,      g_deg);
    cudaGetSymbolAddress((void**)&rowstartb, g_rowstart);
    cudaGetSymbolAddress((void**)&cursorb,   g_cursor);
    cudaGetSymbolAddress((void**)&csrsrcb,   g_csr_src);
    cudaGetSymbolAddress((void**)&poolb,     g_pool);
    cudaGetSymbolAddress((void**)&cntb,      g_cnt);

    __half* w1H = wH;
    __half* w2H = wH + FIN * HEADS * HID;                       // +131072
    __half* w3H = w2H + HEADS * HID * HEADS * HID;              // +262144

    float* node_emb  = (float*)d_out;
    float* graph_emb = (float*)d_out + (size_t)n * HID;

    // ---- fp16 conversions ----
    {
        int n4 = n * FIN / 4;
        f2h_kernel<<<(n4 + 255) / 256, 256>>>(x, xH, n4);
        int w1n = FIN * HEADS * HID / 4;
        f2h_kernel<<<(w1n + 255) / 256, 256>>>(W1, w1H, w1n);
        int w2n = HEADS * HID * HEADS * HID / 4;
        f2h_kernel<<<(w2n + 255) / 256, 256>>>(W2, w2H, w2n);
        int w3n = HEADS * HID * HID / 4;
        f2h_kernel<<<(w3n + 255) / 256, 256>>>(W3, w3H, w3n);
    }

    // ---- CSR build (once, shared by all 3 layers) ----
    cudaMemsetAsync(degb, 0, (size_t)n * sizeof(int));
    deg_kernel<<<(E + 255) / 256, 256>>>(dst, degb, E);
    scan_kernel<<<1, 1024>>>(degb, rowstartb, n);
    cudaMemcpyAsync(cursorb, rowstartb, (size_t)n * sizeof(int), cudaMemcpyDeviceToDevice);
    csr_scatter_kernel<<<(E + 255) / 256, 256>>>(src, dst, cursorb, csrsrcb, E);

    // ---- layers ----
    run_gat_layer(xH, FIN, w1H, a1s, a1d, b1, HEADS, actH, 1, 1,
                  n, rowstartb, csrsrcb, hbuf, alphab);
    run_gat_layer(actH, HEADS * HID, w2H, a2s, a2d, b2, HEADS, actH, 1, 1,
                  n, rowstartb, csrsrcb, hbuf, alphab);
    run_gat_layer(actH, HEADS * HID, w3H, a3s, a3d, b3, 1, node_emb, 0, 0,
                  n, rowstartb, csrsrcb, hbuf, alphab);

    // ---- global mean pool ----
    cudaMemsetAsync(poolb, 0, NGRAPH * HID * sizeof(float));
    cudaMemsetAsync(cntb, 0, NGRAPH * sizeof(float));
    pool_sum_kernel<<<n, HID>>>(node_emb, batch, poolb, cntb, n);
    pool_div_kernel<<<(NGRAPH * HID + 127) / 128, 128>>>(poolb, cntb, graph_emb);
}

// round 11
// speedup vs baseline: 1.0746x; 1.0746x over previous
#include <cuda_runtime.h>
#include <cuda_fp16.h>
#include <cstdint>
#include <cstddef>

#define NN 50000
#define EE 800000
#define FIN 256
#define HID 128
#define HEADS 4
#define NGRAPH 50
#define NEG_SLOPE 0.2f

// ---------------- scratch (device globals; no allocation allowed) -------------
__device__ __half g_hh[(size_t)NN * HEADS * HID];    // GEMM output (fp16 messages)
__device__ __half g_acth[(size_t)NN * HEADS * HID];  // activations (fp16), layer input
__device__ __half g_xh[(size_t)NN * FIN];            // x converted to fp16
__device__ __half g_wh[512 * 512 + 256 * 512 + 512 * 128]; // fp16 weights
__device__ float g_alpha[2 * NN * HEADS];            // [0]=as, [NN*HEADS]=ad
__device__ int   g_deg[NN];
__device__ int   g_rowstart[NN + 1];
__device__ int   g_cursor[NN];
__device__ int   g_csr_src[EE];
__device__ float g_pool[NGRAPH * HID];
__device__ float g_cnt[NGRAPH];

// ==================== fp32 -> fp16 conversion ====================
__global__ void f2h_kernel(const float* __restrict__ in, __half* __restrict__ out, int n4)
{
    int i = blockIdx.x * blockDim.x + threadIdx.x;
    if (i >= n4) return;
    float4 v = ((const float4*)in)[i];
    __half2 a = __float22half2_rn(make_float2(v.x, v.y));
    __half2 b = __float22half2_rn(make_float2(v.z, v.w));
    ((__half2*)out)[2 * i + 0] = a;
    ((__half2*)out)[2 * i + 1] = b;
}

// ==================== fp16 tensor-core GEMM (ldmatrix) + fused alpha epilogue ====================
// C[M,N] = A[M,K] @ B[K,N]; A,B,C fp16, fp32 accumulate. Block tile 128x128,
// BK=64, 256 threads = 8 warps (2m x 4n), warp tile 64x32, mma.m16n8k16.
// A fragments via ldmatrix.x4; B fragments via ldmatrix.x4.trans from [k][n] tile.
__global__ __launch_bounds__(256) void h16_gemm_alpha_kernel(
    const __half* __restrict__ A, const __half* __restrict__ B, __half* __restrict__ C,
    int M, int K, int N,
    const float* __restrict__ a_src, const float* __restrict__ a_dst,  // [H][HID]
    float* __restrict__ as_out, float* __restrict__ ad_out, int H)
{
    __shared__ __align__(16) __half As[128][72];   // [m][k], pitch 72 halfs
    __shared__ __align__(16) __half Bs[64][136];   // [k][n], pitch 136 halfs

    const int tid  = threadIdx.x;
    const int lane = tid & 31;
    const int warp = tid >> 5;
    const int wm = (warp & 1) * 64;
    const int wn = (warp >> 1) * 32;
    const int wnIdx = warp >> 1;

    const int mBase = blockIdx.y * 128;
    const int nBase = blockIdx.x * 128;

    float c[4][4][4];
#pragma unroll
    for (int mi = 0; mi < 4; mi++)
#pragma unroll
        for (int ni = 0; ni < 4; ni++)
#pragma unroll
            for (int q = 0; q < 4; q++) c[mi][ni][q] = 0.f;

    const int g = lane >> 2;
    const int l = lane & 3;

    // ldmatrix lane-address components (computed once)
    const int aRowOff = lane & 15;            // row within 16-row group
    const int aColOff = (lane >> 4) * 8;      // k-half select
    const int bRowOff = (lane & 7) + ((lane >> 3) & 1) * 8;  // k within 16
    const int bColOff = (lane >> 4) * 8;      // n-half select

    for (int k0 = 0; k0 < K; k0 += 64) {
        // ---- load A tile: 128 rows x 64 halfs, uint4 per op ----
#pragma unroll
        for (int p = 0; p < 4; p++) {
            int idx = tid + p * 256;          // 0..1023
            int row = idx >> 3;
            int col = (idx & 7) * 8;
            uint4 v = make_uint4(0u, 0u, 0u, 0u);
            if (mBase + row < M)
                v = *(const uint4*)&A[(size_t)(mBase + row) * K + k0 + col];
            *(uint4*)&As[row][col] = v;
        }
        // ---- load B tile [k][n]: straight coalesced copy ----
#pragma unroll
        for (int p = 0; p < 4; p++) {
            int idx = tid + p * 256;          // 0..1023
            int k = idx >> 4;
            int n8 = (idx & 15) * 8;
            uint4 v = *(const uint4*)&B[(size_t)(k0 + k) * N + nBase + n8];
            *(uint4*)&Bs[k][n8] = v;
        }
        __syncthreads();

#pragma unroll
        for (int kk = 0; kk < 64; kk += 16) {
            uint32_t a[4][4], b[4][2];
#pragma unroll
            for (int mi = 0; mi < 4; mi++) {
                uint32_t addr = (uint32_t)__cvta_generic_to_shared(
                    &As[wm + mi * 16 + aRowOff][kk + aColOff]);
                asm volatile(
                    "ldmatrix.sync.aligned.m8n8.x4.shared.b16 {%0,%1,%2,%3}, [%4];\n"
                    : "=r"(a[mi][0]), "=r"(a[mi][1]), "=r"(a[mi][2]), "=r"(a[mi][3])
                    : "r"(addr));
            }
#pragma unroll
            for (int np = 0; np < 2; np++) {
                uint32_t addr = (uint32_t)__cvta_generic_to_shared(
                    &Bs[kk + bRowOff][wn + np * 16 + bColOff]);
                asm volatile(
                    "ldmatrix.sync.aligned.m8n8.x4.trans.shared.b16 {%0,%1,%2,%3}, [%4];\n"
                    : "=r"(b[2 * np][0]), "=r"(b[2 * np][1]),
                      "=r"(b[2 * np + 1][0]), "=r"(b[2 * np + 1][1])
                    : "r"(addr));
            }
#pragma unroll
            for (int mi = 0; mi < 4; mi++)
#pragma unroll
                for (int ni = 0; ni < 4; ni++) {
                    asm volatile(
                        "mma.sync.aligned.m16n8k16.row.col.f32.f16.f16.f32 "
                        "{%0,%1,%2,%3}, {%4,%5,%6,%7}, {%8,%9}, {%0,%1,%2,%3};\n"
                        : "+f"(c[mi][ni][0]), "+f"(c[mi][ni][1]),
                          "+f"(c[mi][ni][2]), "+f"(c[mi][ni][3])
                        : "r"(a[mi][0]), "r"(a[mi][1]), "r"(a[mi][2]), "r"(a[mi][3]),
                          "r"(b[ni][0]), "r"(b[ni][1]));
                }
        }
        __syncthreads();
    }

    const int hh = nBase / HID;   // head owned by this block column

    // repurpose As smem for the alpha reduction: [128 rows][4 wn][2 (s,d)] floats
    float* s_red = (float*)&As[0][0];

#pragma unroll
    for (int mi = 0; mi < 4; mi++) {
        int r0 = mBase + wm + mi * 16 + g;
        int r1 = r0 + 8;
        float ps0 = 0.f, pd0 = 0.f, ps1 = 0.f, pd1 = 0.f;
#pragma unroll
        for (int ni = 0; ni < 4; ni++) {
            int col = nBase + wn + ni * 8 + 2 * l;
            if (r0 < M)
                *(__half2*)&C[(size_t)r0 * N + col] =
                    __float22half2_rn(make_float2(c[mi][ni][0], c[mi][ni][1]));
            if (r1 < M)
                *(__half2*)&C[(size_t)r1 * N + col] =
                    __float22half2_rn(make_float2(c[mi][ni][2], c[mi][ni][3]));
            int cc = wn + ni * 8 + 2 * l;
            float sa0 = a_src[hh * HID + cc],     sa1 = a_src[hh * HID + cc + 1];
            float da0 = a_dst[hh * HID + cc],     da1 = a_dst[hh * HID + cc + 1];
            ps0 += c[mi][ni][0] * sa0 + c[mi][ni][1] * sa1;
            pd0 += c[mi][ni][0] * da0 + c[mi][ni][1] * da1;
            ps1 += c[mi][ni][2] * sa0 + c[mi][ni][3] * sa1;
            pd1 += c[mi][ni][2] * da0 + c[mi][ni][3] * da1;
        }
#pragma unroll
        for (int o = 1; o <= 2; o <<= 1) {
            ps0 += __shfl_xor_sync(0xffffffffu, ps0, o);
            pd0 += __shfl_xor_sync(0xffffffffu, pd0, o);
            ps1 += __shfl_xor_sync(0xffffffffu, ps1, o);
            pd1 += __shfl_xor_sync(0xffffffffu, pd1, o);
        }
        if (l == 0) {
            int lr0 = wm + mi * 16 + g;
            s_red[(lr0)     * 8 + wnIdx * 2 + 0] = ps0;
            s_red[(lr0)     * 8 + wnIdx * 2 + 1] = pd0;
            s_red[(lr0 + 8) * 8 + wnIdx * 2 + 0] = ps1;
            s_red[(lr0 + 8) * 8 + wnIdx * 2 + 1] = pd1;
        }
    }
    __syncthreads();
    if (tid < 128) {
        int gr = mBase + tid;
        if (gr < M) {
            float as = s_red[tid * 8 + 0] + s_red[tid * 8 + 2] +
                       s_red[tid * 8 + 4] + s_red[tid * 8 + 6];
            float ad = s_red[tid * 8 + 1] + s_red[tid * 8 + 3] +
                       s_red[tid * 8 + 5] + s_red[tid * 8 + 7];
            as_out[gr * H + hh] = as;
            ad_out[gr * H + hh] = ad;
        }
    }
}

// ==================== CSR build ====================
__global__ void deg_kernel(const int* __restrict__ dst, int* __restrict__ deg, int E)
{
    int e = blockIdx.x * blockDim.x + threadIdx.x;
    if (e < E) atomicAdd(&deg[dst[e]], 1);
}

__global__ __launch_bounds__(1024) void scan_kernel(const int* __restrict__ deg,
                                                    int* __restrict__ rowstart, int n)
{
    __shared__ int warp_sums[32];
    __shared__ int s_carry;
    int t = threadIdx.x;
    int lane = t & 31, w = t >> 5;
    if (t == 0) s_carry = 0;
    __syncthreads();
    for (int base = 0; base < n; base += 1024) {
        int i = base + t;
        int x = (i < n) ? deg[i] : 0;
        int v = x;
#pragma unroll
        for (int o = 1; o < 32; o <<= 1) {
            int y = __shfl_up_sync(0xffffffffu, v, o);
            if (lane >= o) v += y;
        }
        if (lane == 31) warp_sums[w] = v;
        __syncthreads();
        if (w == 0) {
            int s = warp_sums[lane];
#pragma unroll
            for (int o = 1; o < 32; o <<= 1) {
                int y = __shfl_up_sync(0xffffffffu, s, o);
                if (lane >= o) s += y;
            }
            warp_sums[lane] = s;
        }
        __syncthreads();
        int prefix = s_carry + (w > 0 ? warp_sums[w - 1] : 0) + v - x;
        if (i < n) rowstart[i] = prefix;
        __syncthreads();
        if (t == 0) s_carry += warp_sums[31];
        __syncthreads();
    }
    if (t == 0) rowstart[n] = s_carry;
}

__global__ void csr_scatter_kernel(const int* __restrict__ src, const int* __restrict__ dst,
                                   int* __restrict__ cursor, int* __restrict__ csr_src, int E)
{
    int e = blockIdx.x * blockDim.x + threadIdx.x;
    if (e >= E) return;
    int p = atomicAdd(&cursor[dst[e]], 1);
    csr_src[p] = src[e];
}

// ==================== FUSED softmax + aggregate + bias + ELU (warp per node) ====================
template <int H, int OUTH>
__global__ __launch_bounds__(256) void gat_fused_kernel(
    const int* __restrict__ rowstart, const int* __restrict__ csr_src,
    const float* __restrict__ as_, const float* __restrict__ ad_,
    const __half* __restrict__ hbuf, const float* __restrict__ bias,
    void* __restrict__ out_, int do_elu, int n)
{
    __shared__ int   s_src[8][32];
    __shared__ float s_cf[8][32][H];

    const int w = threadIdx.x >> 5;
    const int lane = threadIdx.x & 31;
    const int d = blockIdx.x * 8 + w;
    if (d >= n) return;
    const int e0 = rowstart[d];
    const int deg = rowstart[d + 1] - e0;
    const int W = H * HID;
    const int CH = (H == 4) ? 16 : 4;
    const int c0 = lane * CH;
    const int hd = (H == 4) ? (lane >> 3) : 0;
    const float NEG_INF = -__int_as_float(0x7f800000);

    float adv[H];
#pragma unroll
    for (int h = 0; h < H; h++) adv[h] = ad_[d * H + h];

    float acc[16];
#pragma unroll
    for (int i = 0; i < CH; i++) acc[i] = 0.f;

    if (deg <= 32) {
        bool valid = lane < deg;
        int s = 0;
        float v[H];
        if (valid) {
            s = __ldg(&csr_src[e0 + lane]);
            if (H == 4) {
                float4 av = __ldg((const float4*)&as_[s * 4]);
                v[0] = av.x + adv[0]; v[1] = av.y + adv[1];
                v[2] = av.z + adv[2]; v[3] = av.w + adv[3];
            } else {
                v[0] = __ldg(&as_[s]) + adv[0];
            }
#pragma unroll
            for (int h = 0; h < H; h++) v[h] = (v[h] >= 0.f) ? v[h] : NEG_SLOPE * v[h];
        } else {
#pragma unroll
            for (int h = 0; h < H; h++) v[h] = NEG_INF;
        }
#pragma unroll
        for (int h = 0; h < H; h++) {
            float mx = v[h];
#pragma unroll
            for (int o = 16; o; o >>= 1)
                mx = fmaxf(mx, __shfl_xor_sync(0xffffffffu, mx, o));
            float e = valid ? expf(v[h] - mx) : 0.f;
            float sm = e;
#pragma unroll
            for (int o = 16; o; o >>= 1)
                sm += __shfl_xor_sync(0xffffffffu, sm, o);
            v[h] = e / (sm + 1e-16f);
        }
        s_src[w][lane] = s;
#pragma unroll
        for (int h = 0; h < H; h++) s_cf[w][lane][h] = v[h];
        __syncwarp();

#pragma unroll 4
        for (int j = 0; j < deg; j++) {
            int sj = s_src[w][j];
            float cf = s_cf[w][j][hd];
            const __half* hp = hbuf + (size_t)sj * W + c0;
            if (H == 4) {
                uint4 r0 = __ldg((const uint4*)hp);
                uint4 r1 = __ldg((const uint4*)(hp + 8));
                const __half2* p0 = (const __half2*)&r0;
                const __half2* p1 = (const __half2*)&r1;
#pragma unroll
                for (int q = 0; q < 4; q++) {
                    float2 f0 = __half22float2(p0[q]);
                    float2 f1 = __half22float2(p1[q]);
                    acc[2 * q + 0] += f0.x * cf;
                    acc[2 * q + 1] += f0.y * cf;
                    acc[8 + 2 * q + 0] += f1.x * cf;
                    acc[8 + 2 * q + 1] += f1.y * cf;
                }
            } else {
                uint2 r0 = __ldg((const uint2*)hp);
                const __half2* p0 = (const __half2*)&r0;
#pragma unroll
                for (int q = 0; q < 2; q++) {
                    float2 f0 = __half22float2(p0[q]);
                    acc[2 * q + 0] += f0.x * cf;
                    acc[2 * q + 1] += f0.y * cf;
                }
            }
        }
    } else {
        float mx[H], sm[H];
#pragma unroll
        for (int h = 0; h < H; h++) { mx[h] = NEG_INF; sm[h] = 0.f; }
        for (int j = lane; j < deg; j += 32) {
            int s = __ldg(&csr_src[e0 + j]);
#pragma unroll
            for (int h = 0; h < H; h++) {
                float v = as_[s * H + h] + adv[h];
                v = (v >= 0.f) ? v : NEG_SLOPE * v;
                mx[h] = fmaxf(mx[h], v);
            }
        }
#pragma unroll
        for (int h = 0; h < H; h++)
#pragma unroll
            for (int o = 16; o; o >>= 1)
                mx[h] = fmaxf(mx[h], __shfl_xor_sync(0xffffffffu, mx[h], o));
        for (int j = lane; j < deg; j += 32) {
            int s = __ldg(&csr_src[e0 + j]);
#pragma unroll
            for (int h = 0; h < H; h++) {
                float v = as_[s * H + h] + adv[h];
                v = (v >= 0.f) ? v : NEG_SLOPE * v;
                sm[h] += expf(v - mx[h]);
            }
        }
        float inv[H];
#pragma unroll
        for (int h = 0; h < H; h++) {
#pragma unroll
            for (int o = 16; o; o >>= 1)
                sm[h] += __shfl_xor_sync(0xffffffffu, sm[h], o);
            inv[h] = 1.f / (sm[h] + 1e-16f);
        }

        for (int base = 0; base < deg; base += 32) {
            int j = base + lane;
            bool valid = j < deg;
            int s = 0;
            float cf[H];
            if (valid) {
                s = __ldg(&csr_src[e0 + j]);
#pragma unroll
                for (int h = 0; h < H; h++) {
                    float v = as_[s * H + h] + adv[h];
                    v = (v >= 0.f) ? v : NEG_SLOPE * v;
                    cf[h] = expf(v - mx[h]) * inv[h];
                }
            } else {
#pragma unroll
                for (int h = 0; h < H; h++) cf[h] = 0.f;
            }
            __syncwarp();
            s_src[w][lane] = s;
#pragma unroll
            for (int h = 0; h < H; h++) s_cf[w][lane][h] = cf[h];
            __syncwarp();

            int nn = min(32, deg - base);
#pragma unroll 4
            for (int jj = 0; jj < nn; jj++) {
                int sj = s_src[w][jj];
                float cc = s_cf[w][jj][hd];
                const __half* hp = hbuf + (size_t)sj * W + c0;
                if (H == 4) {
                    uint4 r0 = __ldg((const uint4*)hp);
                    uint4 r1 = __ldg((const uint4*)(hp + 8));
                    const __half2* p0 = (const __half2*)&r0;
                    const __half2* p1 = (const __half2*)&r1;
#pragma unroll
                    for (int q = 0; q < 4; q++) {
                        float2 f0 = __half22float2(p0[q]);
                        float2 f1 = __half22float2(p1[q]);
                        acc[2 * q + 0] += f0.x * cc;
                        acc[2 * q + 1] += f0.y * cc;
                        acc[8 + 2 * q + 0] += f1.x * cc;
                        acc[8 + 2 * q + 1] += f1.y * cc;
                    }
                } else {
                    uint2 r0 = __ldg((const uint2*)hp);
                    const __half2* p0 = (const __half2*)&r0;
#pragma unroll
                    for (int q = 0; q < 2; q++) {
                        float2 f0 = __half22float2(p0[q]);
                        acc[2 * q + 0] += f0.x * cc;
                        acc[2 * q + 1] += f0.y * cc;
                    }
                }
            }
        }
    }

    // epilogue: bias + optional ELU, store fp16 or fp32
    float v[16];
#pragma unroll
    for (int i = 0; i < CH; i += 4) {
        float4 b = *(const float4*)&bias[c0 + i];
        v[i + 0] = acc[i + 0] + b.x;
        v[i + 1] = acc[i + 1] + b.y;
        v[i + 2] = acc[i + 2] + b.z;
        v[i + 3] = acc[i + 3] + b.w;
    }
    if (do_elu) {
#pragma unroll
        for (int i = 0; i < CH; i++) v[i] = (v[i] > 0.f) ? v[i] : expm1f(v[i]);
    }
    if (OUTH) {
        __half* out = (__half*)out_;
        __half2 hv[8];
#pragma unroll
        for (int i = 0; i < CH / 2; i++)
            hv[i] = __float22half2_rn(make_float2(v[2 * i], v[2 * i + 1]));
        if (H == 4) {
            *(uint4*)&out[(size_t)d * W + c0]     = *(uint4*)&hv[0];
            *(uint4*)&out[(size_t)d * W + c0 + 8] = *(uint4*)&hv[4];
        } else {
            *(uint2*)&out[(size_t)d * W + c0] = *(uint2*)&hv[0];
        }
    } else {
        float* out = (float*)out_;
#pragma unroll
        for (int i = 0; i < CH; i += 4)
            *(float4*)&out[(size_t)d * W + c0 + i] =
                make_float4(v[i], v[i + 1], v[i + 2], v[i + 3]);
    }
}

// ==================== pooling ====================
__global__ void pool_sum_kernel(const float* __restrict__ node_emb, const int* __restrict__ batch,
                                float* __restrict__ pool, float* __restrict__ cnt, int n)
{
    int node = blockIdx.x;
    int t = threadIdx.x;
    int g = batch[node];
    atomicAdd(&pool[g * HID + t], node_emb[(size_t)node * HID + t]);
    if (t == 0) atomicAdd(&cnt[g], 1.0f);
}

__global__ void pool_div_kernel(const float* __restrict__ pool, const float* __restrict__ cnt,
                                float* __restrict__ out)
{
    int i = blockIdx.x * blockDim.x + threadIdx.x;
    if (i >= NGRAPH * HID) return;
    int g = i / HID;
    out[i] = pool[i] / fmaxf(cnt[g], 1.0f);
}

// ==================== host side ====================
static void run_gat_layer(const __half* inH, int fin,
                          const __half* Wh, const float* a_s, const float* a_d, const float* bias,
                          int heads, void* out, int out_half, int do_elu,
                          int n, const int* rowstart, const int* csr_src,
                          __half* hbuf, float* alphab)
{
    const int width = heads * HID;
    float* asb = alphab;
    float* adb = alphab + NN * HEADS;

    dim3 ggrid(width / 128, (n + 127) / 128);
    h16_gemm_alpha_kernel<<<ggrid, 256>>>(inH, Wh, hbuf, n, fin, width,
                                          a_s, a_d, asb, adb, heads);

    int wgrid = (n + 7) / 8;
    if (heads == 4) {
        if (out_half)
            gat_fused_kernel<4, 1><<<wgrid, 256>>>(rowstart, csr_src, asb, adb, hbuf, bias, out, do_elu, n);
        else
            gat_fused_kernel<4, 0><<<wgrid, 256>>>(rowstart, csr_src, asb, adb, hbuf, bias, out, do_elu, n);
    } else {
        gat_fused_kernel<1, 0><<<wgrid, 256>>>(rowstart, csr_src, asb, adb, hbuf, bias, out, do_elu, n);
    }
}

extern "C" void kernel_launch(void* const* d_in, const int* in_sizes, int n_in,
                              void* d_out, int out_size)
{
    const float* x     = (const float*)d_in[0];
    const int*   ei    = (const int*)d_in[1];
    const int*   batch = (const int*)d_in[2];
    const float* W1  = (const float*)d_in[3];
    const float* a1s = (const float*)d_in[4];
    const float* a1d = (const float*)d_in[5];
    const float* b1  = (const float*)d_in[6];
    const float* W2  = (const float*)d_in[7];
    const float* a2s = (const float*)d_in[8];
    const float* a2d = (const float*)d_in[9];
    const float* b2  = (const float*)d_in[10];
    const float* W3  = (const float*)d_in[11];
    const float* a3s = (const float*)d_in[12];
    const float* a3d = (const float*)d_in[13];
    const float* b3  = (const float*)d_in[14];

    const int n = in_sizes[0] / FIN;
    const int E = in_sizes[1] / 2;
    const int* src = ei;
    const int* dst = ei + E;

    float *alphab, *poolb, *cntb;
    __half *hbuf, *actH, *xH, *wH;
    int *degb, *rowstartb, *cursorb, *csrsrcb;
    cudaGetSymbolAddress((void**)&hbuf,      g_hh);
    cudaGetSymbolAddress((void**)&actH,      g_acth);
    cudaGetSymbolAddress((void**)&xH,        g_xh);
    cudaGetSymbolAddress((void**)&wH,        g_wh);
    cudaGetSymbolAddress((void**)&alphab,    g_alpha);
    cudaGetSymbolAddress((void**)&degb,      g_deg);
    cudaGetSymbolAddress((void**)&rowstartb, g_rowstart);
    cudaGetSymbolAddress((void**)&cursorb,   g_cursor);
    cudaGetSymbolAddress((void**)&csrsrcb,   g_csr_src);
    cudaGetSymbolAddress((void**)&poolb,     g_pool);
    cudaGetSymbolAddress((void**)&cntb,      g_cnt);

    __half* w1H = wH;
    __half* w2H = wH + FIN * HEADS * HID;
    __half* w3H = w2H + HEADS * HID * HEADS * HID;

    float* node_emb  = (float*)d_out;
    float* graph_emb = (float*)d_out + (size_t)n * HID;

    // ---- fp16 conversions ----
    {
        int n4 = n * FIN / 4;
        f2h_kernel<<<(n4 + 255) / 256, 256>>>(x, xH, n4);
        int w1n = FIN * HEADS * HID / 4;
        f2h_kernel<<<(w1n + 255) / 256, 256>>>(W1, w1H, w1n);
        int w2n = HEADS * HID * HEADS * HID / 4;
        f2h_kernel<<<(w2n + 255) / 256, 256>>>(W2, w2H, w2n);
        int w3n = HEADS * HID * HID / 4;
        f2h_kernel<<<(w3n + 255) / 256, 256>>>(W3, w3H, w3n);
    }

    // ---- CSR build (once, shared by all 3 layers) ----
    cudaMemsetAsync(degb, 0, (size_t)n * sizeof(int));
    deg_kernel<<<(E + 255) / 256, 256>>>(dst, degb, E);
    scan_kernel<<<1, 1024>>>(degb, rowstartb, n);
    cudaMemcpyAsync(cursorb, rowstartb, (size_t)n * sizeof(int), cudaMemcpyDeviceToDevice);
    csr_scatter_kernel<<<(E + 255) / 256, 256>>>(src, dst, cursorb, csrsrcb, E);

    // ---- layers ----
    run_gat_layer(xH, FIN, w1H, a1s, a1d, b1, HEADS, actH, 1, 1,
                  n, rowstartb, csrsrcb, hbuf, alphab);
    run_gat_layer(actH, HEADS * HID, w2H, a2s, a2d, b2, HEADS, actH, 1, 1,
                  n, rowstartb, csrsrcb, hbuf, alphab);
    run_gat_layer(actH, HEADS * HID, w3H, a3s, a3d, b3, 1, node_emb, 0, 0,
                  n, rowstartb, csrsrcb, hbuf, alphab);

    // ---- global mean pool ----
    cudaMemsetAsync(poolb, 0, NGRAPH * HID * sizeof(float));
    cudaMemsetAsync(cntb, 0, NGRAPH * sizeof(float));
    pool_sum_kernel<<<n, HID>>>(node_emb, batch, poolb, cntb, n);
    pool_div_kernel<<<(NGRAPH * HID + 127) / 128, 128>>>(poolb, cntb, graph_emb);
}

// round 13
// speedup vs baseline: 1.5847x; 1.4747x over previous
#include <cuda_runtime.h>
#include <cuda_fp16.h>
#include <cstdint>
#include <cstddef>

#define NN 50000
#define EE 800000
#define FIN 256
#define HID 128
#define HEADS 4
#define NGRAPH 50
#define NEG_SLOPE 0.2f

// ---------------- scratch (device globals; no allocation allowed) -------------
__device__ __half g_hh[(size_t)NN * HEADS * HID];    // GEMM output (fp16 messages)
__device__ __half g_acth[(size_t)NN * HEADS * HID];  // activations (fp16), layer input
__device__ __half g_xh[(size_t)NN * FIN];            // x converted to fp16
__device__ __half g_wh[512 * 512 + 256 * 512 + 512 * 128]; // fp16 weights
__device__ float g_alpha[2 * NN * HEADS];            // [0]=as, [NN*HEADS]=ad
__device__ int   g_deg[NN];
__device__ int   g_rowstart[NN + 1];
__device__ int   g_cursor[NN];
__device__ int   g_csr_src[EE];
__device__ float g_pool[NGRAPH * HID];
__device__ float g_cnt[NGRAPH];

// ==================== fp32 -> fp16 conversion ====================
__global__ void f2h_kernel(const float* __restrict__ in, __half* __restrict__ out, int n4)
{
    int i = blockIdx.x * blockDim.x + threadIdx.x;
    if (i >= n4) return;
    float4 v = ((const float4*)in)[i];
    __half2 a = __float22half2_rn(make_float2(v.x, v.y));
    __half2 b = __float22half2_rn(make_float2(v.z, v.w));
    ((__half2*)out)[2 * i + 0] = a;
    ((__half2*)out)[2 * i + 1] = b;
}

// ==================== cp.async helpers ====================
__device__ __forceinline__ void cp_async16(uint32_t smem_addr, const void* gptr, bool valid)
{
    int sz = valid ? 16 : 0;
    asm volatile("cp.async.cg.shared.global [%0], [%1], 16, %2;\n"
                 :: "r"(smem_addr), "l"(gptr), "r"(sz));
}
__device__ __forceinline__ void cp_commit() { asm volatile("cp.async.commit_group;\n"); }
__device__ __forceinline__ void cp_wait1()  { asm volatile("cp.async.wait_group 1;\n"); }
__device__ __forceinline__ void cp_wait0()  { asm volatile("cp.async.wait_group 0;\n"); }

// ==================== fp16 GEMM: cp.async double-buffered, ldmatrix, m16n8k16 ====================
// C[M,N] = A[M,K] @ B[K,N]; fp32 accumulate. Block tile 128x128, BK=32,
// 256 threads = 8 warps (2m x 4n), warp tile 64x32. Fused alpha epilogue.
__global__ __launch_bounds__(256) void h16_gemm_alpha_kernel(
    const __half* __restrict__ A, const __half* __restrict__ B, __half* __restrict__ C,
    int M, int K, int N,
    const float* __restrict__ a_src, const float* __restrict__ a_dst,  // [H][HID]
    float* __restrict__ as_out, float* __restrict__ ad_out, int H)
{
    __shared__ __align__(16) __half As[2][128][40];   // [m][k], pitch 40 halfs (80B)
    __shared__ __align__(16) __half Bs[2][32][136];   // [k][n], pitch 136 halfs (272B)

    const int tid  = threadIdx.x;
    const int lane = tid & 31;
    const int warp = tid >> 5;
    const int wm = (warp & 1) * 64;
    const int wn = (warp >> 1) * 32;
    const int wnIdx = warp >> 1;

    const int mBase = blockIdx.y * 128;
    const int nBase = blockIdx.x * 128;

    float c[4][4][4];
#pragma unroll
    for (int mi = 0; mi < 4; mi++)
#pragma unroll
        for (int ni = 0; ni < 4; ni++)
#pragma unroll
            for (int q = 0; q < 4; q++) c[mi][ni][q] = 0.f;

    const int g = lane >> 2;
    const int l = lane & 3;

    // ldmatrix lane-address components
    const int aRowOff = lane & 15;
    const int aColOff = (lane >> 4) * 8;
    const int bRowOff = (lane & 7) + ((lane >> 3) & 1) * 8;
    const int bColOff = (lane >> 4) * 8;

    // tile-load index precompute (2 uint4 per thread per tile each for A and B)
    const int aRow0 = tid >> 2;               // p=0: rows 0..63
    const int aCol0 = (tid & 3) * 8;
    const int bK0   = tid >> 4;               // p=0: k 0..15
    const int bN0   = (tid & 15) * 8;

    const int T = K >> 5;   // BK=32 tiles

    // ---- prologue: stage 0 ----
    {
        int k0 = 0;
#pragma unroll
        for (int p = 0; p < 2; p++) {
            int row = aRow0 + p * 64;
            bool v = (mBase + row) < M;
            uint32_t sa = (uint32_t)__cvta_generic_to_shared(&As[0][row][aCol0]);
            cp_async16(sa, &A[(size_t)(mBase + row) * K + k0 + aCol0], v);
        }
#pragma unroll
        for (int p = 0; p < 2; p++) {
            int k = bK0 + p * 16;
            uint32_t sb = (uint32_t)__cvta_generic_to_shared(&Bs[0][k][bN0]);
            cp_async16(sb, &B[(size_t)(k0 + k) * N + nBase + bN0], true);
        }
        cp_commit();
    }

    for (int t = 0; t < T; t++) {
        int buf = t & 1;
        // issue next stage
        if (t + 1 < T) {
            int k0 = (t + 1) << 5;
            int nbuf = buf ^ 1;
#pragma unroll
            for (int p = 0; p < 2; p++) {
                int row = aRow0 + p * 64;
                bool v = (mBase + row) < M;
                uint32_t sa = (uint32_t)__cvta_generic_to_shared(&As[nbuf][row][aCol0]);
                cp_async16(sa, &A[(size_t)(mBase + row) * K + k0 + aCol0], v);
            }
#pragma unroll
            for (int p = 0; p < 2; p++) {
                int k = bK0 + p * 16;
                uint32_t sb = (uint32_t)__cvta_generic_to_shared(&Bs[nbuf][k][bN0]);
                cp_async16(sb, &B[(size_t)(k0 + k) * N + nBase + bN0], true);
            }
            cp_commit();
            cp_wait1();
        } else {
            cp_wait0();
        }
        __syncthreads();

        // compute on buf: 2 k-steps of 16
#pragma unroll
        for (int kk = 0; kk < 32; kk += 16) {
            uint32_t a[4][4], b[4][2];
#pragma unroll
            for (int mi = 0; mi < 4; mi++) {
                uint32_t addr = (uint32_t)__cvta_generic_to_shared(
                    &As[buf][wm + mi * 16 + aRowOff][kk + aColOff]);
                asm volatile(
                    "ldmatrix.sync.aligned.m8n8.x4.shared.b16 {%0,%1,%2,%3}, [%4];\n"
                    : "=r"(a[mi][0]), "=r"(a[mi][1]), "=r"(a[mi][2]), "=r"(a[mi][3])
                    : "r"(addr));
            }
#pragma unroll
            for (int np = 0; np < 2; np++) {
                uint32_t addr = (uint32_t)__cvta_generic_to_shared(
                    &Bs[buf][kk + bRowOff][wn + np * 16 + bColOff]);
                asm volatile(
                    "ldmatrix.sync.aligned.m8n8.x4.trans.shared.b16 {%0,%1,%2,%3}, [%4];\n"
                    : "=r"(b[2 * np][0]), "=r"(b[2 * np][1]),
                      "=r"(b[2 * np + 1][0]), "=r"(b[2 * np + 1][1])
                    : "r"(addr));
            }
#pragma unroll
            for (int mi = 0; mi < 4; mi++)
#pragma unroll
                for (int ni = 0; ni < 4; ni++) {
                    asm volatile(
                        "mma.sync.aligned.m16n8k16.row.col.f32.f16.f16.f32 "
                        "{%0,%1,%2,%3}, {%4,%5,%6,%7}, {%8,%9}, {%0,%1,%2,%3};\n"
                        : "+f"(c[mi][ni][0]), "+f"(c[mi][ni][1]),
                          "+f"(c[mi][ni][2]), "+f"(c[mi][ni][3])
                        : "r"(a[mi][0]), "r"(a[mi][1]), "r"(a[mi][2]), "r"(a[mi][3]),
                          "r"(b[ni][0]), "r"(b[ni][1]));
                }
        }
        __syncthreads();
    }

    const int hh = nBase / HID;   // head owned by this block column

    // repurpose As smem for the alpha reduction: [128 rows][4 wn][2 (s,d)] floats
    float* s_red = (float*)&As[0][0][0];

#pragma unroll
    for (int mi = 0; mi < 4; mi++) {
        int r0 = mBase + wm + mi * 16 + g;
        int r1 = r0 + 8;
        float ps0 = 0.f, pd0 = 0.f, ps1 = 0.f, pd1 = 0.f;
#pragma unroll
        for (int ni = 0; ni < 4; ni++) {
            int col = nBase + wn + ni * 8 + 2 * l;
            if (r0 < M)
                *(__half2*)&C[(size_t)r0 * N + col] =
                    __float22half2_rn(make_float2(c[mi][ni][0], c[mi][ni][1]));
            if (r1 < M)
                *(__half2*)&C[(size_t)r1 * N + col] =
                    __float22half2_rn(make_float2(c[mi][ni][2], c[mi][ni][3]));
            int cc = wn + ni * 8 + 2 * l;
            float sa0 = a_src[hh * HID + cc],     sa1 = a_src[hh * HID + cc + 1];
            float da0 = a_dst[hh * HID + cc],     da1 = a_dst[hh * HID + cc + 1];
            ps0 += c[mi][ni][0] * sa0 + c[mi][ni][1] * sa1;
            pd0 += c[mi][ni][0] * da0 + c[mi][ni][1] * da1;
            ps1 += c[mi][ni][2] * sa0 + c[mi][ni][3] * sa1;
            pd1 += c[mi][ni][2] * da0 + c[mi][ni][3] * da1;
        }
#pragma unroll
        for (int o = 1; o <= 2; o <<= 1) {
            ps0 += __shfl_xor_sync(0xffffffffu, ps0, o);
            pd0 += __shfl_xor_sync(0xffffffffu, pd0, o);
            ps1 += __shfl_xor_sync(0xffffffffu, ps1, o);
            pd1 += __shfl_xor_sync(0xffffffffu, pd1, o);
        }
        if (l == 0) {
            int lr0 = wm + mi * 16 + g;
            s_red[(lr0)     * 8 + wnIdx * 2 + 0] = ps0;
            s_red[(lr0)     * 8 + wnIdx * 2 + 1] = pd0;
            s_red[(lr0 + 8) * 8 + wnIdx * 2 + 0] = ps1;
            s_red[(lr0 + 8) * 8 + wnIdx * 2 + 1] = pd1;
        }
    }
    __syncthreads();
    if (tid < 128) {
        int gr = mBase + tid;
        if (gr < M) {
            float as = s_red[tid * 8 + 0] + s_red[tid * 8 + 2] +
                       s_red[tid * 8 + 4] + s_red[tid * 8 + 6];
            float ad = s_red[tid * 8 + 1] + s_red[tid * 8 + 3] +
                       s_red[tid * 8 + 5] + s_red[tid * 8 + 7];
            as_out[gr * H + hh] = as;
            ad_out[gr * H + hh] = ad;
        }
    }
}

// ==================== CSR build ====================
__global__ void deg_kernel(const int* __restrict__ dst, int* __restrict__ deg, int E)
{
    int e = blockIdx.x * blockDim.x + threadIdx.x;
    if (e < E) atomicAdd(&deg[dst[e]], 1);
}

__global__ __launch_bounds__(1024) void scan_kernel(const int* __restrict__ deg,
                                                    int* __restrict__ rowstart, int n)
{
    __shared__ int warp_sums[32];
    __shared__ int s_carry;
    int t = threadIdx.x;
    int lane = t & 31, w = t >> 5;
    if (t == 0) s_carry = 0;
    __syncthreads();
    for (int base = 0; base < n; base += 1024) {
        int i = base + t;
        int x = (i < n) ? deg[i] : 0;
        int v = x;
#pragma unroll
        for (int o = 1; o < 32; o <<= 1) {
            int y = __shfl_up_sync(0xffffffffu, v, o);
            if (lane >= o) v += y;
        }
        if (lane == 31) warp_sums[w] = v;
        __syncthreads();
        if (w == 0) {
            int s = warp_sums[lane];
#pragma unroll
            for (int o = 1; o < 32; o <<= 1) {
                int y = __shfl_up_sync(0xffffffffu, s, o);
                if (lane >= o) s += y;
            }
            warp_sums[lane] = s;
        }
        __syncthreads();
        int prefix = s_carry + (w > 0 ? warp_sums[w - 1] : 0) + v - x;
        if (i < n) rowstart[i] = prefix;
        __syncthreads();
        if (t == 0) s_carry += warp_sums[31];
        __syncthreads();
    }
    if (t == 0) rowstart[n] = s_carry;
}

__global__ void csr_scatter_kernel(const int* __restrict__ src, const int* __restrict__ dst,
                                   int* __restrict__ cursor, int* __restrict__ csr_src, int E)
{
    int e = blockIdx.x * blockDim.x + threadIdx.x;
    if (e >= E) return;
    int p = atomicAdd(&cursor[dst[e]], 1);
    csr_src[p] = src[e];
}

// ==================== FUSED softmax + aggregate + bias + ELU (warp per node) ====================
template <int H, int OUTH>
__global__ __launch_bounds__(256) void gat_fused_kernel(
    const int* __restrict__ rowstart, const int* __restrict__ csr_src,
    const float* __restrict__ as_, const float* __restrict__ ad_,
    const __half* __restrict__ hbuf, const float* __restrict__ bias,
    void* __restrict__ out_, int do_elu, int n)
{
    __shared__ int   s_src[8][32];
    __shared__ float s_cf[8][32][H];

    const int w = threadIdx.x >> 5;
    const int lane = threadIdx.x & 31;
    const int d = blockIdx.x * 8 + w;
    if (d >= n) return;
    const int e0 = rowstart[d];
    const int deg = rowstart[d + 1] - e0;
    const int W = H * HID;
    const int CH = (H == 4) ? 16 : 4;
    const int c0 = lane * CH;
    const int hd = (H == 4) ? (lane >> 3) : 0;
    const float NEG_INF = -__int_as_float(0x7f800000);

    float adv[H];
#pragma unroll
    for (int h = 0; h < H; h++) adv[h] = ad_[d * H + h];

    float acc[16];
#pragma unroll
    for (int i = 0; i < CH; i++) acc[i] = 0.f;

    if (deg <= 32) {
        bool valid = lane < deg;
        int s = 0;
        float v[H];
        if (valid) {
            s = __ldg(&csr_src[e0 + lane]);
            if (H == 4) {
                float4 av = __ldg((const float4*)&as_[s * 4]);
                v[0] = av.x + adv[0]; v[1] = av.y + adv[1];
                v[2] = av.z + adv[2]; v[3] = av.w + adv[3];
            } else {
                v[0] = __ldg(&as_[s]) + adv[0];
            }
#pragma unroll
            for (int h = 0; h < H; h++) v[h] = (v[h] >= 0.f) ? v[h] : NEG_SLOPE * v[h];
        } else {
#pragma unroll
            for (int h = 0; h < H; h++) v[h] = NEG_INF;
        }
#pragma unroll
        for (int h = 0; h < H; h++) {
            float mx = v[h];
#pragma unroll
            for (int o = 16; o; o >>= 1)
                mx = fmaxf(mx, __shfl_xor_sync(0xffffffffu, mx, o));
            float e = valid ? expf(v[h] - mx) : 0.f;
            float sm = e;
#pragma unroll
            for (int o = 16; o; o >>= 1)
                sm += __shfl_xor_sync(0xffffffffu, sm, o);
            v[h] = e / (sm + 1e-16f);
        }
        s_src[w][lane] = s;
#pragma unroll
        for (int h = 0; h < H; h++) s_cf[w][lane][h] = v[h];
        __syncwarp();

#pragma unroll 4
        for (int j = 0; j < deg; j++) {
            int sj = s_src[w][j];
            float cf = s_cf[w][j][hd];
            const __half* hp = hbuf + (size_t)sj * W + c0;
            if (H == 4) {
                uint4 r0 = __ldg((const uint4*)hp);
                uint4 r1 = __ldg((const uint4*)(hp + 8));
                const __half2* p0 = (const __half2*)&r0;
                const __half2* p1 = (const __half2*)&r1;
#pragma unroll
                for (int q = 0; q < 4; q++) {
                    float2 f0 = __half22float2(p0[q]);
                    float2 f1 = __half22float2(p1[q]);
                    acc[2 * q + 0] += f0.x * cf;
                    acc[2 * q + 1] += f0.y * cf;
                    acc[8 + 2 * q + 0] += f1.x * cf;
                    acc[8 + 2 * q + 1] += f1.y * cf;
                }
            } else {
                uint2 r0 = __ldg((const uint2*)hp);
                const __half2* p0 = (const __half2*)&r0;
#pragma unroll
                for (int q = 0; q < 2; q++) {
                    float2 f0 = __half22float2(p0[q]);
                    acc[2 * q + 0] += f0.x * cf;
                    acc[2 * q + 1] += f0.y * cf;
                }
            }
        }
    } else {
        float mx[H], sm[H];
#pragma unroll
        for (int h = 0; h < H; h++) { mx[h] = NEG_INF; sm[h] = 0.f; }
        for (int j = lane; j < deg; j += 32) {
            int s = __ldg(&csr_src[e0 + j]);
#pragma unroll
            for (int h = 0; h < H; h++) {
                float v = as_[s * H + h] + adv[h];
                v = (v >= 0.f) ? v : NEG_SLOPE * v;
                mx[h] = fmaxf(mx[h], v);
            }
        }
#pragma unroll
        for (int h = 0; h < H; h++)
#pragma unroll
            for (int o = 16; o; o >>= 1)
                mx[h] = fmaxf(mx[h], __shfl_xor_sync(0xffffffffu, mx[h], o));
        for (int j = lane; j < deg; j += 32) {
            int s = __ldg(&csr_src[e0 + j]);
#pragma unroll
            for (int h = 0; h < H; h++) {
                float v = as_[s * H + h] + adv[h];
                v = (v >= 0.f) ? v : NEG_SLOPE * v;
                sm[h] += expf(v - mx[h]);
            }
        }
        float inv[H];
#pragma unroll
        for (int h = 0; h < H; h++) {
#pragma unroll
            for (int o = 16; o; o >>= 1)
                sm[h] += __shfl_xor_sync(0xffffffffu, sm[h], o);
            inv[h] = 1.f / (sm[h] + 1e-16f);
        }

        for (int base = 0; base < deg; base += 32) {
            int j = base + lane;
            bool valid = j < deg;
            int s = 0;
            float cf[H];
            if (valid) {
                s = __ldg(&csr_src[e0 + j]);
#pragma unroll
                for (int h = 0; h < H; h++) {
                    float v = as_[s * H + h] + adv[h];
                    v = (v >= 0.f) ? v : NEG_SLOPE * v;
                    cf[h] = expf(v - mx[h]) * inv[h];
                }
            } else {
#pragma unroll
                for (int h = 0; h < H; h++) cf[h] = 0.f;
            }
            __syncwarp();
            s_src[w][lane] = s;
#pragma unroll
            for (int h = 0; h < H; h++) s_cf[w][lane][h] = cf[h];
            __syncwarp();

            int nn = min(32, deg - base);
#pragma unroll 4
            for (int jj = 0; jj < nn; jj++) {
                int sj = s_src[w][jj];
                float cc = s_cf[w][jj][hd];
                const __half* hp = hbuf + (size_t)sj * W + c0;
                if (H == 4) {
                    uint4 r0 = __ldg((const uint4*)hp);
                    uint4 r1 = __ldg((const uint4*)(hp + 8));
                    const __half2* p0 = (const __half2*)&r0;
                    const __half2* p1 = (const __half2*)&r1;
#pragma unroll
                    for (int q = 0; q < 4; q++) {
                        float2 f0 = __half22float2(p0[q]);
                        float2 f1 = __half22float2(p1[q]);
                        acc[2 * q + 0] += f0.x * cc;
                        acc[2 * q + 1] += f0.y * cc;
                        acc[8 + 2 * q + 0] += f1.x * cc;
                        acc[8 + 2 * q + 1] += f1.y * cc;
                    }
                } else {
                    uint2 r0 = __ldg((const uint2*)hp);
                    const __half2* p0 = (const __half2*)&r0;
#pragma unroll
                    for (int q = 0; q < 2; q++) {
                        float2 f0 = __half22float2(p0[q]);
                        acc[2 * q + 0] += f0.x * cc;
                        acc[2 * q + 1] += f0.y * cc;
                    }
                }
            }
        }
    }

    // epilogue: bias + optional ELU, store fp16 or fp32
    float v[16];
#pragma unroll
    for (int i = 0; i < CH; i += 4) {
        float4 b = *(const float4*)&bias[c0 + i];
        v[i + 0] = acc[i + 0] + b.x;
        v[i + 1] = acc[i + 1] + b.y;
        v[i + 2] = acc[i + 2] + b.z;
        v[i + 3] = acc[i + 3] + b.w;
    }
    if (do_elu) {
#pragma unroll
        for (int i = 0; i < CH; i++) v[i] = (v[i] > 0.f) ? v[i] : expm1f(v[i]);
    }
    if (OUTH) {
        __half* out = (__half*)out_;
        __half2 hv[8];
#pragma unroll
        for (int i = 0; i < CH / 2; i++)
            hv[i] = __float22half2_rn(make_float2(v[2 * i], v[2 * i + 1]));
        if (H == 4) {
            *(uint4*)&out[(size_t)d * W + c0]     = *(uint4*)&hv[0];
            *(uint4*)&out[(size_t)d * W + c0 + 8] = *(uint4*)&hv[4];
        } else {
            *(uint2*)&out[(size_t)d * W + c0] = *(uint2*)&hv[0];
        }
    } else {
        float* out = (float*)out_;
#pragma unroll
        for (int i = 0; i < CH; i += 4)
            *(float4*)&out[(size_t)d * W + c0 + i] =
                make_float4(v[i], v[i + 1], v[i + 2], v[i + 3]);
    }
}

// ==================== pooling ====================
__global__ void pool_sum_kernel(const float* __restrict__ node_emb, const int* __restrict__ batch,
                                float* __restrict__ pool, float* __restrict__ cnt, int n)
{
    int node = blockIdx.x;
    int t = threadIdx.x;
    int g = batch[node];
    atomicAdd(&pool[g * HID + t], node_emb[(size_t)node * HID + t]);
    if (t == 0) atomicAdd(&cnt[g], 1.0f);
}

__global__ void pool_div_kernel(const float* __restrict__ pool, const float* __restrict__ cnt,
                                float* __restrict__ out)
{
    int i = blockIdx.x * blockDim.x + threadIdx.x;
    if (i >= NGRAPH * HID) return;
    int g = i / HID;
    out[i] = pool[i] / fmaxf(cnt[g], 1.0f);
}

// ==================== host side ====================
static void run_gat_layer(const __half* inH, int fin,
                          const __half* Wh, const float* a_s, const float* a_d, const float* bias,
                          int heads, void* out, int out_half, int do_elu,
                          int n, const int* rowstart, const int* csr_src,
                          __half* hbuf, float* alphab)
{
    const int width = heads * HID;
    float* asb = alphab;
    float* adb = alphab + NN * HEADS;

    dim3 ggrid(width / 128, (n + 127) / 128);
    h16_gemm_alpha_kernel<<<ggrid, 256>>>(inH, Wh, hbuf, n, fin, width,
                                          a_s, a_d, asb, adb, heads);

    int wgrid = (n + 7) / 8;
    if (heads == 4) {
        if (out_half)
            gat_fused_kernel<4, 1><<<wgrid, 256>>>(rowstart, csr_src, asb, adb, hbuf, bias, out, do_elu, n);
        else
            gat_fused_kernel<4, 0><<<wgrid, 256>>>(rowstart, csr_src, asb, adb, hbuf, bias, out, do_elu, n);
    } else {
        gat_fused_kernel<1, 0><<<wgrid, 256>>>(rowstart, csr_src, asb, adb, hbuf, bias, out, do_elu, n);
    }
}

extern "C" void kernel_launch(void* const* d_in, const int* in_sizes, int n_in,
                              void* d_out, int out_size)
{
    const float* x     = (const float*)d_in[0];
    const int*   ei    = (const int*)d_in[1];
    const int*   batch = (const int*)d_in[2];
    const float* W1  = (const float*)d_in[3];
    const float* a1s = (const float*)d_in[4];
    const float* a1d = (const float*)d_in[5];
    const float* b1  = (const float*)d_in[6];
    const float* W2  = (const float*)d_in[7];
    const float* a2s = (const float*)d_in[8];
    const float* a2d = (const float*)d_in[9];
    const float* b2  = (const float*)d_in[10];
    const float* W3  = (const float*)d_in[11];
    const float* a3s = (const float*)d_in[12];
    const float* a3d = (const float*)d_in[13];
    const float* b3  = (const float*)d_in[14];

    const int n = in_sizes[0] / FIN;
    const int E = in_sizes[1] / 2;
    const int* src = ei;
    const int* dst = ei + E;

    float *alphab, *poolb, *cntb;
    __half *hbuf, *actH, *xH, *wH;
    int *degb, *rowstartb, *cursorb, *csrsrcb;
    cudaGetSymbolAddress((void**)&hbuf,      g_hh);
    cudaGetSymbolAddress((void**)&actH,      g_acth);
    cudaGetSymbolAddress((void**)&xH,        g_xh);
    cudaGetSymbolAddress((void**)&wH,        g_wh);
    cudaGetSymbolAddress((void**)&alphab,    g_alpha);
    cudaGetSymbolAddress((void**)&degb,      g_deg);
    cudaGetSymbolAddress((void**)&rowstartb, g_rowstart);
    cudaGetSymbolAddress((void**)&cursorb,   g_cursor);
    cudaGetSymbolAddress((void**)&csrsrcb,   g_csr_src);
    cudaGetSymbolAddress((void**)&poolb,     g_pool);
    cudaGetSymbolAddress((void**)&cntb,      g_cnt);

    __half* w1H = wH;
    __half* w2H = wH + FIN * HEADS * HID;
    __half* w3H = w2H + HEADS * HID * HEADS * HID;

    float* node_emb  = (float*)d_out;
    float* graph_emb = (float*)d_out + (size_t)n * HID;

    // ---- fp16 conversions ----
    {
        int n4 = n * FIN / 4;
        f2h_kernel<<<(n4 + 255) / 256, 256>>>(x, xH, n4);
        int w1n = FIN * HEADS * HID / 4;
        f2h_kernel<<<(w1n + 255) / 256, 256>>>(W1, w1H, w1n);
        int w2n = HEADS * HID * HEADS * HID / 4;
        f2h_kernel<<<(w2n + 255) / 256, 256>>>(W2, w2H, w2n);
        int w3n = HEADS * HID * HID / 4;
        f2h_kernel<<<(w3n + 255) / 256, 256>>>(W3, w3H, w3n);
    }

    // ---- CSR build (once, shared by all 3 layers) ----
    cudaMemsetAsync(degb, 0, (size_t)n * sizeof(int));
    deg_kernel<<<(E + 255) / 256, 256>>>(dst, degb, E);
    scan_kernel<<<1, 1024>>>(degb, rowstartb, n);
    cudaMemcpyAsync(cursorb, rowstartb, (size_t)n * sizeof(int), cudaMemcpyDeviceToDevice);
    csr_scatter_kernel<<<(E + 255) / 256, 256>>>(src, dst, cursorb, csrsrcb, E);

    // ---- layers ----
    run_gat_layer(xH, FIN, w1H, a1s, a1d, b1, HEADS, actH, 1, 1,
                  n, rowstartb, csrsrcb, hbuf, alphab);
    run_gat_layer(actH, HEADS * HID, w2H, a2s, a2d, b2, HEADS, actH, 1, 1,
                  n, rowstartb, csrsrcb, hbuf, alphab);
    run_gat_layer(actH, HEADS * HID, w3H, a3s, a3d, b3, 1, node_emb, 0, 0,
                  n, rowstartb, csrsrcb, hbuf, alphab);

    // ---- global mean pool ----
    cudaMemsetAsync(poolb, 0, NGRAPH * HID * sizeof(float));
    cudaMemsetAsync(cntb, 0, NGRAPH * sizeof(float));
    pool_sum_kernel<<<n, HID>>>(node_emb, batch, poolb, cntb, n);
    pool_div_kernel<<<(NGRAPH * HID + 127) / 128, 128>>>(poolb, cntb, graph_emb);
}

// round 14
// speedup vs baseline: 1.5907x; 1.0038x over previous
#include <cuda_runtime.h>
#include <cuda_fp16.h>
#include <cstdint>
#include <cstddef>

#define NN 50000
#define EE 800000
#define FIN 256
#define HID 128
#define HEADS 4
#define NGRAPH 50
#define NEG_SLOPE 0.2f

// ---------------- scratch (device globals; no allocation allowed) -------------
__device__ __half g_hh[(size_t)NN * HEADS * HID];    // GEMM output (fp16 messages)
__device__ __half g_acth[(size_t)NN * HEADS * HID];  // activations (fp16), layer input
__device__ __half g_xh[(size_t)NN * FIN];            // x converted to fp16
__device__ __half g_wh[512 * 512 + 256 * 512 + 512 * 128]; // fp16 weights
__device__ float g_alpha[2 * NN * HEADS];            // [0]=as, [NN*HEADS]=ad
__device__ int   g_deg[NN];
__device__ int   g_rowstart[NN + 1];
__device__ int   g_cursor[NN];
__device__ int   g_csr_src[EE];
__device__ float g_pool[NGRAPH * HID];
__device__ float g_cnt[NGRAPH];

// ==================== fp32 -> fp16 conversion ====================
__global__ void f2h_kernel(const float* __restrict__ in, __half* __restrict__ out, int n4)
{
    int i = blockIdx.x * blockDim.x + threadIdx.x;
    if (i >= n4) return;
    float4 v = ((const float4*)in)[i];
    __half2 a = __float22half2_rn(make_float2(v.x, v.y));
    __half2 b = __float22half2_rn(make_float2(v.z, v.w));
    ((__half2*)out)[2 * i + 0] = a;
    ((__half2*)out)[2 * i + 1] = b;
}

// ==================== cp.async helpers ====================
__device__ __forceinline__ void cp_async16(uint32_t smem_addr, const void* gptr, bool valid)
{
    int sz = valid ? 16 : 0;
    asm volatile("cp.async.cg.shared.global [%0], [%1], 16, %2;\n"
                 :: "r"(smem_addr), "l"(gptr), "r"(sz));
}
__device__ __forceinline__ void cp_commit() { asm volatile("cp.async.commit_group;\n"); }
__device__ __forceinline__ void cp_wait1()  { asm volatile("cp.async.wait_group 1;\n"); }
__device__ __forceinline__ void cp_wait0()  { asm volatile("cp.async.wait_group 0;\n"); }

// ==================== fp16 GEMM: cp.async double-buffered, ldmatrix, m16n8k16 ====================
__global__ __launch_bounds__(256) void h16_gemm_alpha_kernel(
    const __half* __restrict__ A, const __half* __restrict__ B, __half* __restrict__ C,
    int M, int K, int N,
    const float* __restrict__ a_src, const float* __restrict__ a_dst,  // [H][HID]
    float* __restrict__ as_out, float* __restrict__ ad_out, int H)
{
    __shared__ __align__(16) __half As[2][128][40];   // [m][k], pitch 40 halfs
    __shared__ __align__(16) __half Bs[2][32][136];   // [k][n], pitch 136 halfs

    const int tid  = threadIdx.x;
    const int lane = tid & 31;
    const int warp = tid >> 5;
    const int wm = (warp & 1) * 64;
    const int wn = (warp >> 1) * 32;
    const int wnIdx = warp >> 1;

    const int mBase = blockIdx.y * 128;
    const int nBase = blockIdx.x * 128;

    float c[4][4][4];
#pragma unroll
    for (int mi = 0; mi < 4; mi++)
#pragma unroll
        for (int ni = 0; ni < 4; ni++)
#pragma unroll
            for (int q = 0; q < 4; q++) c[mi][ni][q] = 0.f;

    const int g = lane >> 2;
    const int l = lane & 3;

    const int aRowOff = lane & 15;
    const int aColOff = (lane >> 4) * 8;
    const int bRowOff = (lane & 7) + ((lane >> 3) & 1) * 8;
    const int bColOff = (lane >> 4) * 8;

    const int aRow0 = tid >> 2;
    const int aCol0 = (tid & 3) * 8;
    const int bK0   = tid >> 4;
    const int bN0   = (tid & 15) * 8;

    const int T = K >> 5;

    {
        int k0 = 0;
#pragma unroll
        for (int p = 0; p < 2; p++) {
            int row = aRow0 + p * 64;
            bool v = (mBase + row) < M;
            uint32_t sa = (uint32_t)__cvta_generic_to_shared(&As[0][row][aCol0]);
            cp_async16(sa, &A[(size_t)(mBase + row) * K + k0 + aCol0], v);
        }
#pragma unroll
        for (int p = 0; p < 2; p++) {
            int k = bK0 + p * 16;
            uint32_t sb = (uint32_t)__cvta_generic_to_shared(&Bs[0][k][bN0]);
            cp_async16(sb, &B[(size_t)(k0 + k) * N + nBase + bN0], true);
        }
        cp_commit();
    }

    for (int t = 0; t < T; t++) {
        int buf = t & 1;
        if (t + 1 < T) {
            int k0 = (t + 1) << 5;
            int nbuf = buf ^ 1;
#pragma unroll
            for (int p = 0; p < 2; p++) {
                int row = aRow0 + p * 64;
                bool v = (mBase + row) < M;
                uint32_t sa = (uint32_t)__cvta_generic_to_shared(&As[nbuf][row][aCol0]);
                cp_async16(sa, &A[(size_t)(mBase + row) * K + k0 + aCol0], v);
            }
#pragma unroll
            for (int p = 0; p < 2; p++) {
                int k = bK0 + p * 16;
                uint32_t sb = (uint32_t)__cvta_generic_to_shared(&Bs[nbuf][k][bN0]);
                cp_async16(sb, &B[(size_t)(k0 + k) * N + nBase + bN0], true);
            }
            cp_commit();
            cp_wait1();
        } else {
            cp_wait0();
        }
        __syncthreads();

#pragma unroll
        for (int kk = 0; kk < 32; kk += 16) {
            uint32_t a[4][4], b[4][2];
#pragma unroll
            for (int mi = 0; mi < 4; mi++) {
                uint32_t addr = (uint32_t)__cvta_generic_to_shared(
                    &As[buf][wm + mi * 16 + aRowOff][kk + aColOff]);
                asm volatile(
                    "ldmatrix.sync.aligned.m8n8.x4.shared.b16 {%0,%1,%2,%3}, [%4];\n"
                    : "=r"(a[mi][0]), "=r"(a[mi][1]), "=r"(a[mi][2]), "=r"(a[mi][3])
                    : "r"(addr));
            }
#pragma unroll
            for (int np = 0; np < 2; np++) {
                uint32_t addr = (uint32_t)__cvta_generic_to_shared(
                    &Bs[buf][kk + bRowOff][wn + np * 16 + bColOff]);
                asm volatile(
                    "ldmatrix.sync.aligned.m8n8.x4.trans.shared.b16 {%0,%1,%2,%3}, [%4];\n"
                    : "=r"(b[2 * np][0]), "=r"(b[2 * np][1]),
                      "=r"(b[2 * np + 1][0]), "=r"(b[2 * np + 1][1])
                    : "r"(addr));
            }
#pragma unroll
            for (int mi = 0; mi < 4; mi++)
#pragma unroll
                for (int ni = 0; ni < 4; ni++) {
                    asm volatile(
                        "mma.sync.aligned.m16n8k16.row.col.f32.f16.f16.f32 "
                        "{%0,%1,%2,%3}, {%4,%5,%6,%7}, {%8,%9}, {%0,%1,%2,%3};\n"
                        : "+f"(c[mi][ni][0]), "+f"(c[mi][ni][1]),
                          "+f"(c[mi][ni][2]), "+f"(c[mi][ni][3])
                        : "r"(a[mi][0]), "r"(a[mi][1]), "r"(a[mi][2]), "r"(a[mi][3]),
                          "r"(b[ni][0]), "r"(b[ni][1]));
                }
        }
        __syncthreads();
    }

    const int hh = nBase / HID;

    float* s_red = (float*)&As[0][0][0];

#pragma unroll
    for (int mi = 0; mi < 4; mi++) {
        int r0 = mBase + wm + mi * 16 + g;
        int r1 = r0 + 8;
        float ps0 = 0.f, pd0 = 0.f, ps1 = 0.f, pd1 = 0.f;
#pragma unroll
        for (int ni = 0; ni < 4; ni++) {
            int col = nBase + wn + ni * 8 + 2 * l;
            if (r0 < M)
                *(__half2*)&C[(size_t)r0 * N + col] =
                    __float22half2_rn(make_float2(c[mi][ni][0], c[mi][ni][1]));
            if (r1 < M)
                *(__half2*)&C[(size_t)r1 * N + col] =
                    __float22half2_rn(make_float2(c[mi][ni][2], c[mi][ni][3]));
            int cc = wn + ni * 8 + 2 * l;
            float sa0 = a_src[hh * HID + cc],     sa1 = a_src[hh * HID + cc + 1];
            float da0 = a_dst[hh * HID + cc],     da1 = a_dst[hh * HID + cc + 1];
            ps0 += c[mi][ni][0] * sa0 + c[mi][ni][1] * sa1;
            pd0 += c[mi][ni][0] * da0 + c[mi][ni][1] * da1;
            ps1 += c[mi][ni][2] * sa0 + c[mi][ni][3] * sa1;
            pd1 += c[mi][ni][2] * da0 + c[mi][ni][3] * da1;
        }
#pragma unroll
        for (int o = 1; o <= 2; o <<= 1) {
            ps0 += __shfl_xor_sync(0xffffffffu, ps0, o);
            pd0 += __shfl_xor_sync(0xffffffffu, pd0, o);
            ps1 += __shfl_xor_sync(0xffffffffu, ps1, o);
            pd1 += __shfl_xor_sync(0xffffffffu, pd1, o);
        }
        if (l == 0) {
            int lr0 = wm + mi * 16 + g;
            s_red[(lr0)     * 8 + wnIdx * 2 + 0] = ps0;
            s_red[(lr0)     * 8 + wnIdx * 2 + 1] = pd0;
            s_red[(lr0 + 8) * 8 + wnIdx * 2 + 0] = ps1;
            s_red[(lr0 + 8) * 8 + wnIdx * 2 + 1] = pd1;
        }
    }
    __syncthreads();
    if (tid < 128) {
        int gr = mBase + tid;
        if (gr < M) {
            float as = s_red[tid * 8 + 0] + s_red[tid * 8 + 2] +
                       s_red[tid * 8 + 4] + s_red[tid * 8 + 6];
            float ad = s_red[tid * 8 + 1] + s_red[tid * 8 + 3] +
                       s_red[tid * 8 + 5] + s_red[tid * 8 + 7];
            as_out[gr * H + hh] = as;
            ad_out[gr * H + hh] = ad;
        }
    }
}

// ==================== CSR build ====================
__global__ void deg_kernel(const int* __restrict__ dst, int* __restrict__ deg, int E)
{
    int e = blockIdx.x * blockDim.x + threadIdx.x;
    if (e < E) atomicAdd(&deg[dst[e]], 1);
}

__global__ __launch_bounds__(1024) void scan_kernel(const int* __restrict__ deg,
                                                    int* __restrict__ rowstart, int n)
{
    __shared__ int warp_sums[32];
    __shared__ int s_carry;
    int t = threadIdx.x;
    int lane = t & 31, w = t >> 5;
    if (t == 0) s_carry = 0;
    __syncthreads();
    for (int base = 0; base < n; base += 1024) {
        int i = base + t;
        int x = (i < n) ? deg[i] : 0;
        int v = x;
#pragma unroll
        for (int o = 1; o < 32; o <<= 1) {
            int y = __shfl_up_sync(0xffffffffu, v, o);
            if (lane >= o) v += y;
        }
        if (lane == 31) warp_sums[w] = v;
        __syncthreads();
        if (w == 0) {
            int s = warp_sums[lane];
#pragma unroll
            for (int o = 1; o < 32; o <<= 1) {
                int y = __shfl_up_sync(0xffffffffu, s, o);
                if (lane >= o) s += y;
            }
            warp_sums[lane] = s;
        }
        __syncthreads();
        int prefix = s_carry + (w > 0 ? warp_sums[w - 1] : 0) + v - x;
        if (i < n) rowstart[i] = prefix;
        __syncthreads();
        if (t == 0) s_carry += warp_sums[31];
        __syncthreads();
    }
    if (t == 0) rowstart[n] = s_carry;
}

__global__ void csr_scatter_kernel(const int* __restrict__ src, const int* __restrict__ dst,
                                   int* __restrict__ cursor, int* __restrict__ csr_src, int E)
{
    int e = blockIdx.x * blockDim.x + threadIdx.x;
    if (e >= E) return;
    int p = atomicAdd(&cursor[dst[e]], 1);
    csr_src[p] = src[e];
}

// ==================== FUSED aggregate, H=4: TWO warps per node (one per head pair) ====
// Each warp handles 2 heads = 256 channels; lane owns 8 channels (one LDG.128/edge).
// Always ELU + fp16 store (layers 1-2).
__global__ __launch_bounds__(256) void gat_fused4_kernel(
    const int* __restrict__ rowstart, const int* __restrict__ csr_src,
    const float* __restrict__ as_, const float* __restrict__ ad_,
    const __half* __restrict__ hbuf, const float* __restrict__ bias,
    __half* __restrict__ out, int n)
{
    __shared__ int   s_src[8][32];
    __shared__ float s_cf[8][32][2];

    const int w = threadIdx.x >> 5;            // 0..7
    const int lane = threadIdx.x & 31;
    const int d = blockIdx.x * 4 + (w >> 1);   // node
    const int hp = w & 1;                      // head pair (heads 2hp, 2hp+1)
    if (d >= n) return;
    const int e0 = rowstart[d];
    const int deg = rowstart[d + 1] - e0;
    const int c0 = hp * 256 + lane * 8;        // channel base (8 fp16 = 16B)
    const int hsel = lane >> 4;                // which head of the pair (0/1)
    const float NEG_INF = -__int_as_float(0x7f800000);

    float2 advv = *(const float2*)&ad_[d * 4 + hp * 2];

    float acc[8];
#pragma unroll
    for (int i = 0; i < 8; i++) acc[i] = 0.f;

    if (deg <= 32) {
        // ---- fast path: one edge per lane, single 8B gather of as_ pair ----
        bool valid = lane < deg;
        int s = 0;
        float v0, v1;
        if (valid) {
            s = __ldg(&csr_src[e0 + lane]);
            float2 av = __ldg((const float2*)&as_[s * 4 + hp * 2]);
            v0 = av.x + advv.x; v0 = (v0 >= 0.f) ? v0 : NEG_SLOPE * v0;
            v1 = av.y + advv.y; v1 = (v1 >= 0.f) ? v1 : NEG_SLOPE * v1;
        } else { v0 = NEG_INF; v1 = NEG_INF; }

        float mx0 = v0, mx1 = v1;
#pragma unroll
        for (int o = 16; o; o >>= 1) {
            mx0 = fmaxf(mx0, __shfl_xor_sync(0xffffffffu, mx0, o));
            mx1 = fmaxf(mx1, __shfl_xor_sync(0xffffffffu, mx1, o));
        }
        float e0f = valid ? expf(v0 - mx0) : 0.f;
        float e1f = valid ? expf(v1 - mx1) : 0.f;
        float sm0 = e0f, sm1 = e1f;
#pragma unroll
        for (int o = 16; o; o >>= 1) {
            sm0 += __shfl_xor_sync(0xffffffffu, sm0, o);
            sm1 += __shfl_xor_sync(0xffffffffu, sm1, o);
        }
        s_src[w][lane] = s;
        s_cf[w][lane][0] = e0f / (sm0 + 1e-16f);
        s_cf[w][lane][1] = e1f / (sm1 + 1e-16f);
        __syncwarp();

#pragma unroll 4
        for (int j = 0; j < deg; j++) {
            int sj = s_src[w][j];
            float cf = s_cf[w][j][hsel];
            uint4 r0 = __ldg((const uint4*)(hbuf + (size_t)sj * 512 + c0));
            const __half2* p0 = (const __half2*)&r0;
#pragma unroll
            for (int q = 0; q < 4; q++) {
                float2 f0 = __half22float2(p0[q]);
                acc[2 * q + 0] += f0.x * cf;
                acc[2 * q + 1] += f0.y * cf;
            }
        }
    } else {
        // ---- generic path ----
        float mx0 = NEG_INF, mx1 = NEG_INF, sm0 = 0.f, sm1 = 0.f;
        for (int j = lane; j < deg; j += 32) {
            int s = __ldg(&csr_src[e0 + j]);
            float2 av = __ldg((const float2*)&as_[s * 4 + hp * 2]);
            float v0 = av.x + advv.x; v0 = (v0 >= 0.f) ? v0 : NEG_SLOPE * v0;
            float v1 = av.y + advv.y; v1 = (v1 >= 0.f) ? v1 : NEG_SLOPE * v1;
            mx0 = fmaxf(mx0, v0); mx1 = fmaxf(mx1, v1);
        }
#pragma unroll
        for (int o = 16; o; o >>= 1) {
            mx0 = fmaxf(mx0, __shfl_xor_sync(0xffffffffu, mx0, o));
            mx1 = fmaxf(mx1, __shfl_xor_sync(0xffffffffu, mx1, o));
        }
        for (int j = lane; j < deg; j += 32) {
            int s = __ldg(&csr_src[e0 + j]);
            float2 av = __ldg((const float2*)&as_[s * 4 + hp * 2]);
            float v0 = av.x + advv.x; v0 = (v0 >= 0.f) ? v0 : NEG_SLOPE * v0;
            float v1 = av.y + advv.y; v1 = (v1 >= 0.f) ? v1 : NEG_SLOPE * v1;
            sm0 += expf(v0 - mx0); sm1 += expf(v1 - mx1);
        }
#pragma unroll
        for (int o = 16; o; o >>= 1) {
            sm0 += __shfl_xor_sync(0xffffffffu, sm0, o);
            sm1 += __shfl_xor_sync(0xffffffffu, sm1, o);
        }
        float inv0 = 1.f / (sm0 + 1e-16f);
        float inv1 = 1.f / (sm1 + 1e-16f);

        for (int base = 0; base < deg; base += 32) {
            int j = base + lane;
            bool valid = j < deg;
            int s = 0;
            float cf0 = 0.f, cf1 = 0.f;
            if (valid) {
                s = __ldg(&csr_src[e0 + j]);
                float2 av = __ldg((const float2*)&as_[s * 4 + hp * 2]);
                float v0 = av.x + advv.x; v0 = (v0 >= 0.f) ? v0 : NEG_SLOPE * v0;
                float v1 = av.y + advv.y; v1 = (v1 >= 0.f) ? v1 : NEG_SLOPE * v1;
                cf0 = expf(v0 - mx0) * inv0;
                cf1 = expf(v1 - mx1) * inv1;
            }
            __syncwarp();
            s_src[w][lane] = s;
            s_cf[w][lane][0] = cf0;
            s_cf[w][lane][1] = cf1;
            __syncwarp();

            int nn = min(32, deg - base);
#pragma unroll 4
            for (int jj = 0; jj < nn; jj++) {
                int sj = s_src[w][jj];
                float cf = s_cf[w][jj][hsel];
                uint4 r0 = __ldg((const uint4*)(hbuf + (size_t)sj * 512 + c0));
                const __half2* p0 = (const __half2*)&r0;
#pragma unroll
                for (int q = 0; q < 4; q++) {
                    float2 f0 = __half22float2(p0[q]);
                    acc[2 * q + 0] += f0.x * cf;
                    acc[2 * q + 1] += f0.y * cf;
                }
            }
        }
    }

    // epilogue: bias + ELU, fp16 store (one uint4)
    float v[8];
#pragma unroll
    for (int i = 0; i < 8; i += 4) {
        float4 b = *(const float4*)&bias[c0 + i];
        v[i + 0] = acc[i + 0] + b.x;
        v[i + 1] = acc[i + 1] + b.y;
        v[i + 2] = acc[i + 2] + b.z;
        v[i + 3] = acc[i + 3] + b.w;
    }
#pragma unroll
    for (int i = 0; i < 8; i++) v[i] = (v[i] > 0.f) ? v[i] : expm1f(v[i]);
    __half2 hv[4];
#pragma unroll
    for (int i = 0; i < 4; i++)
        hv[i] = __float22half2_rn(make_float2(v[2 * i], v[2 * i + 1]));
    *(uint4*)&out[(size_t)d * 512 + c0] = *(uint4*)&hv[0];
}

// ==================== FUSED aggregate, H=1: warp per node, fp32 out, no ELU ====
__global__ __launch_bounds__(256) void gat_fused1_kernel(
    const int* __restrict__ rowstart, const int* __restrict__ csr_src,
    const float* __restrict__ as_, const float* __restrict__ ad_,
    const __half* __restrict__ hbuf, const float* __restrict__ bias,
    float* __restrict__ out, int n)
{
    __shared__ int   s_src[8][32];
    __shared__ float s_cf[8][32];

    const int w = threadIdx.x >> 5;
    const int lane = threadIdx.x & 31;
    const int d = blockIdx.x * 8 + w;
    if (d >= n) return;
    const int e0 = rowstart[d];
    const int deg = rowstart[d + 1] - e0;
    const int c0 = lane * 4;
    const float NEG_INF = -__int_as_float(0x7f800000);

    float adv = ad_[d];

    float acc[4] = {0.f, 0.f, 0.f, 0.f};

    if (deg <= 32) {
        bool valid = lane < deg;
        int s = 0;
        float v0;
        if (valid) {
            s = __ldg(&csr_src[e0 + lane]);
            v0 = __ldg(&as_[s]) + adv;
            v0 = (v0 >= 0.f) ? v0 : NEG_SLOPE * v0;
        } else v0 = NEG_INF;
        float mx = v0;
#pragma unroll
        for (int o = 16; o; o >>= 1)
            mx = fmaxf(mx, __shfl_xor_sync(0xffffffffu, mx, o));
        float e = valid ? expf(v0 - mx) : 0.f;
        float sm = e;
#pragma unroll
        for (int o = 16; o; o >>= 1)
            sm += __shfl_xor_sync(0xffffffffu, sm, o);
        s_src[w][lane] = s;
        s_cf[w][lane] = e / (sm + 1e-16f);
        __syncwarp();

#pragma unroll 4
        for (int j = 0; j < deg; j++) {
            int sj = s_src[w][j];
            float cf = s_cf[w][j];
            uint2 r0 = __ldg((const uint2*)(hbuf + (size_t)sj * HID + c0));
            const __half2* p0 = (const __half2*)&r0;
#pragma unroll
            for (int q = 0; q < 2; q++) {
                float2 f0 = __half22float2(p0[q]);
                acc[2 * q + 0] += f0.x * cf;
                acc[2 * q + 1] += f0.y * cf;
            }
        }
    } else {
        float mx = NEG_INF, sm = 0.f;
        for (int j = lane; j < deg; j += 32) {
            int s = __ldg(&csr_src[e0 + j]);
            float v = __ldg(&as_[s]) + adv;
            v = (v >= 0.f) ? v : NEG_SLOPE * v;
            mx = fmaxf(mx, v);
        }
#pragma unroll
        for (int o = 16; o; o >>= 1)
            mx = fmaxf(mx, __shfl_xor_sync(0xffffffffu, mx, o));
        for (int j = lane; j < deg; j += 32) {
            int s = __ldg(&csr_src[e0 + j]);
            float v = __ldg(&as_[s]) + adv;
            v = (v >= 0.f) ? v : NEG_SLOPE * v;
            sm += expf(v - mx);
        }
#pragma unroll
        for (int o = 16; o; o >>= 1)
            sm += __shfl_xor_sync(0xffffffffu, sm, o);
        float inv = 1.f / (sm + 1e-16f);

        for (int base = 0; base < deg; base += 32) {
            int j = base + lane;
            bool valid = j < deg;
            int s = 0;
            float cf = 0.f;
            if (valid) {
                s = __ldg(&csr_src[e0 + j]);
                float v = __ldg(&as_[s]) + adv;
                v = (v >= 0.f) ? v : NEG_SLOPE * v;
                cf = expf(v - mx) * inv;
            }
            __syncwarp();
            s_src[w][lane] = s;
            s_cf[w][lane] = cf;
            __syncwarp();

            int nn = min(32, deg - base);
#pragma unroll 4
            for (int jj = 0; jj < nn; jj++) {
                int sj = s_src[w][jj];
                float c = s_cf[w][jj];
                uint2 r0 = __ldg((const uint2*)(hbuf + (size_t)sj * HID + c0));
                const __half2* p0 = (const __half2*)&r0;
#pragma unroll
                for (int q = 0; q < 2; q++) {
                    float2 f0 = __half22float2(p0[q]);
                    acc[2 * q + 0] += f0.x * c;
                    acc[2 * q + 1] += f0.y * c;
                }
            }
        }
    }

    float4 b = *(const float4*)&bias[c0];
    *(float4*)&out[(size_t)d * HID + c0] =
        make_float4(acc[0] + b.x, acc[1] + b.y, acc[2] + b.z, acc[3] + b.w);
}

// ==================== pooling ====================
__global__ void pool_sum_kernel(const float* __restrict__ node_emb, const int* __restrict__ batch,
                                float* __restrict__ pool, float* __restrict__ cnt, int n)
{
    int node = blockIdx.x;
    int t = threadIdx.x;
    int g = batch[node];
    atomicAdd(&pool[g * HID + t], node_emb[(size_t)node * HID + t]);
    if (t == 0) atomicAdd(&cnt[g], 1.0f);
}

__global__ void pool_div_kernel(const float* __restrict__ pool, const float* __restrict__ cnt,
                                float* __restrict__ out)
{
    int i = blockIdx.x * blockDim.x + threadIdx.x;
    if (i >= NGRAPH * HID) return;
    int g = i / HID;
    out[i] = pool[i] / fmaxf(cnt[g], 1.0f);
}

// ==================== host side ====================
extern "C" void kernel_launch(void* const* d_in, const int* in_sizes, int n_in,
                              void* d_out, int out_size)
{
    const float* x     = (const float*)d_in[0];
    const int*   ei    = (const int*)d_in[1];
    const int*   batch = (const int*)d_in[2];
    const float* W1  = (const float*)d_in[3];
    const float* a1s = (const float*)d_in[4];
    const float* a1d = (const float*)d_in[5];
    const float* b1  = (const float*)d_in[6];
    const float* W2  = (const float*)d_in[7];
    const float* a2s = (const float*)d_in[8];
    const float* a2d = (const float*)d_in[9];
    const float* b2  = (const float*)d_in[10];
    const float* W3  = (const float*)d_in[11];
    const float* a3s = (const float*)d_in[12];
    const float* a3d = (const float*)d_in[13];
    const float* b3  = (const float*)d_in[14];

    const int n = in_sizes[0] / FIN;
    const int E = in_sizes[1] / 2;
    const int* src = ei;
    const int* dst = ei + E;

    float *alphab, *poolb, *cntb;
    __half *hbuf, *actH, *xH, *wH;
    int *degb, *rowstartb, *cursorb, *csrsrcb;
    cudaGetSymbolAddress((void**)&hbuf,      g_hh);
    cudaGetSymbolAddress((void**)&actH,      g_acth);
    cudaGetSymbolAddress((void**)&xH,        g_xh);
    cudaGetSymbolAddress((void**)&wH,        g_wh);
    cudaGetSymbolAddress((void**)&alphab,    g_alpha);
    cudaGetSymbolAddress((void**)&degb,      g_deg);
    cudaGetSymbolAddress((void**)&rowstartb, g_rowstart);
    cudaGetSymbolAddress((void**)&cursorb,   g_cursor);
    cudaGetSymbolAddress((void**)&csrsrcb,   g_csr_src);
    cudaGetSymbolAddress((void**)&poolb,     g_pool);
    cudaGetSymbolAddress((void**)&cntb,      g_cnt);

    __half* w1H = wH;
    __half* w2H = wH + FIN * HEADS * HID;
    __half* w3H = w2H + HEADS * HID * HEADS * HID;

    float* asb = alphab;
    float* adb = alphab + NN * HEADS;

    float* node_emb  = (float*)d_out;
    float* graph_emb = (float*)d_out + (size_t)n * HID;

    // ---- fp16 conversions ----
    {
        int n4 = n * FIN / 4;
        f2h_kernel<<<(n4 + 255) / 256, 256>>>(x, xH, n4);
        int w1n = FIN * HEADS * HID / 4;
        f2h_kernel<<<(w1n + 255) / 256, 256>>>(W1, w1H, w1n);
        int w2n = HEADS * HID * HEADS * HID / 4;
        f2h_kernel<<<(w2n + 255) / 256, 256>>>(W2, w2H, w2n);
        int w3n = HEADS * HID * HID / 4;
        f2h_kernel<<<(w3n + 255) / 256, 256>>>(W3, w3H, w3n);
    }

    // ---- CSR build (once, shared by all 3 layers) ----
    cudaMemsetAsync(degb, 0, (size_t)n * sizeof(int));
    deg_kernel<<<(E + 255) / 256, 256>>>(dst, degb, E);
    scan_kernel<<<1, 1024>>>(degb, rowstartb, n);
    cudaMemcpyAsync(cursorb, rowstartb, (size_t)n * sizeof(int), cudaMemcpyDeviceToDevice);
    csr_scatter_kernel<<<(E + 255) / 256, 256>>>(src, dst, cursorb, csrsrcb, E);

    // ---- layer 1 ----
    {
        dim3 ggrid(4, (n + 127) / 128);
        h16_gemm_alpha_kernel<<<ggrid, 256>>>(xH, w1H, hbuf, n, FIN, 512,
                                              a1s, a1d, asb, adb, 4);
        gat_fused4_kernel<<<(n + 3) / 4, 256>>>(rowstartb, csrsrcb, asb, adb,
                                                hbuf, b1, actH, n);
    }
    // ---- layer 2 ----
    {
        dim3 ggrid(4, (n + 127) / 128);
        h16_gemm_alpha_kernel<<<ggrid, 256>>>(actH, w2H, hbuf, n, 512, 512,
                                              a2s, a2d, asb, adb, 4);
        gat_fused4_kernel<<<(n + 3) / 4, 256>>>(rowstartb, csrsrcb, asb, adb,
                                                hbuf, b2, actH, n);
    }
    // ---- layer 3 ----
    {
        dim3 ggrid(1, (n + 127) / 128);
        h16_gemm_alpha_kernel<<<ggrid, 256>>>(actH, w3H, hbuf, n, 512, 128,
                                              a3s, a3d, asb, adb, 1);
        gat_fused1_kernel<<<(n + 7) / 8, 256>>>(rowstartb, csrsrcb, asb, adb,
                                                hbuf, b3, node_emb, n);
    }

    // ---- global mean pool ----
    cudaMemsetAsync(poolb, 0, NGRAPH * HID * sizeof(float));
    cudaMemsetAsync(cntb, 0, NGRAPH * sizeof(float));
    pool_sum_kernel<<<n, HID>>>(node_emb, batch, poolb, cntb, n);
    pool_div_kernel<<<(NGRAPH * HID + 127) / 128, 128>>>(poolb, cntb, graph_emb);
}

// round 15
// speedup vs baseline: 1.6021x; 1.0072x over previous
#include <cuda_runtime.h>
#include <cuda_fp16.h>
#include <cstdint>
#include <cstddef>

#define NN 50000
#define EE 800000
#define FIN 256
#define HID 128
#define HEADS 4
#define NGRAPH 50
#define NEG_SLOPE 0.2f

// ---------------- scratch (device globals; no allocation allowed) -------------
__device__ __half g_hh[(size_t)NN * HEADS * HID];    // GEMM output (fp16 messages)
__device__ __half g_acth[(size_t)NN * HEADS * HID];  // activations (fp16), layer input
__device__ __half g_xh[(size_t)NN * FIN];            // x converted to fp16
__device__ __half g_wh[512 * 512 + 256 * 512 + 512 * 128]; // fp16 weights
__device__ float g_alpha[2 * NN * HEADS];            // [0]=as, [NN*HEADS]=ad
__device__ int   g_deg[NN];
__device__ int   g_rowstart[NN + 1];
__device__ int   g_cursor[NN];
__device__ int   g_csr_src[EE];
__device__ float g_pool[NGRAPH * HID];
__device__ float g_cnt[NGRAPH];

// ==================== fused fp32 -> fp16 conversion (x + 3 weights) ============
__global__ void f2h_all_kernel(const float* __restrict__ x,
                               const float* __restrict__ w1,
                               const float* __restrict__ w2,
                               const float* __restrict__ w3,
                               __half* __restrict__ xH,
                               __half* __restrict__ w1H,
                               __half* __restrict__ w2H,
                               __half* __restrict__ w3H,
                               int nx4)   // x float4 count
{
    const int t1 = FIN * HEADS * HID / 4;           // 32768
    const int t2 = HEADS * HID * HEADS * HID / 4;   // 65536
    const int t3 = HEADS * HID * HID / 4;           // 16384
    int total = nx4 + t1 + t2 + t3;
    for (int i = blockIdx.x * blockDim.x + threadIdx.x; i < total;
         i += gridDim.x * blockDim.x) {
        const float* in; __half* out; int j;
        if (i < nx4)                { in = x;  out = xH;  j = i; }
        else if (i < nx4 + t1)      { in = w1; out = w1H; j = i - nx4; }
        else if (i < nx4 + t1 + t2) { in = w2; out = w2H; j = i - nx4 - t1; }
        else                        { in = w3; out = w3H; j = i - nx4 - t1 - t2; }
        float4 v = ((const float4*)in)[j];
        __half2 a = __float22half2_rn(make_float2(v.x, v.y));
        __half2 b = __float22half2_rn(make_float2(v.z, v.w));
        ((__half2*)out)[2 * j + 0] = a;
        ((__half2*)out)[2 * j + 1] = b;
    }
}

// ==================== cp.async helpers ====================
__device__ __forceinline__ void cp_async16(uint32_t smem_addr, const void* gptr, bool valid)
{
    int sz = valid ? 16 : 0;
    asm volatile("cp.async.cg.shared.global [%0], [%1], 16, %2;\n"
                 :: "r"(smem_addr), "l"(gptr), "r"(sz));
}
__device__ __forceinline__ void cp_commit() { asm volatile("cp.async.commit_group;\n"); }
__device__ __forceinline__ void cp_wait1()  { asm volatile("cp.async.wait_group 1;\n"); }
__device__ __forceinline__ void cp_wait0()  { asm volatile("cp.async.wait_group 0;\n"); }

// ==================== fp16 GEMM: cp.async double-buffered, ldmatrix, m16n8k16 ====================
__global__ __launch_bounds__(256) void h16_gemm_alpha_kernel(
    const __half* __restrict__ A, const __half* __restrict__ B, __half* __restrict__ C,
    int M, int K, int N,
    const float* __restrict__ a_src, const float* __restrict__ a_dst,  // [H][HID]
    float* __restrict__ as_out, float* __restrict__ ad_out, int H)
{
    __shared__ __align__(16) __half As[2][128][40];   // [m][k], pitch 40 halfs
    __shared__ __align__(16) __half Bs[2][32][136];   // [k][n], pitch 136 halfs

    const int tid  = threadIdx.x;
    const int lane = tid & 31;
    const int warp = tid >> 5;
    const int wm = (warp & 1) * 64;
    const int wn = (warp >> 1) * 32;
    const int wnIdx = warp >> 1;

    const int mBase = blockIdx.y * 128;
    const int nBase = blockIdx.x * 128;

    float c[4][4][4];
#pragma unroll
    for (int mi = 0; mi < 4; mi++)
#pragma unroll
        for (int ni = 0; ni < 4; ni++)
#pragma unroll
            for (int q = 0; q < 4; q++) c[mi][ni][q] = 0.f;

    const int g = lane >> 2;
    const int l = lane & 3;

    const int aRowOff = lane & 15;
    const int aColOff = (lane >> 4) * 8;
    const int bRowOff = (lane & 7) + ((lane >> 3) & 1) * 8;
    const int bColOff = (lane >> 4) * 8;

    const int aRow0 = tid >> 2;
    const int aCol0 = (tid & 3) * 8;
    const int bK0   = tid >> 4;
    const int bN0   = (tid & 15) * 8;

    const int T = K >> 5;

    {
        int k0 = 0;
#pragma unroll
        for (int p = 0; p < 2; p++) {
            int row = aRow0 + p * 64;
            bool v = (mBase + row) < M;
            uint32_t sa = (uint32_t)__cvta_generic_to_shared(&As[0][row][aCol0]);
            cp_async16(sa, &A[(size_t)(mBase + row) * K + k0 + aCol0], v);
        }
#pragma unroll
        for (int p = 0; p < 2; p++) {
            int k = bK0 + p * 16;
            uint32_t sb = (uint32_t)__cvta_generic_to_shared(&Bs[0][k][bN0]);
            cp_async16(sb, &B[(size_t)(k0 + k) * N + nBase + bN0], true);
        }
        cp_commit();
    }

    for (int t = 0; t < T; t++) {
        int buf = t & 1;
        if (t + 1 < T) {
            int k0 = (t + 1) << 5;
            int nbuf = buf ^ 1;
#pragma unroll
            for (int p = 0; p < 2; p++) {
                int row = aRow0 + p * 64;
                bool v = (mBase + row) < M;
                uint32_t sa = (uint32_t)__cvta_generic_to_shared(&As[nbuf][row][aCol0]);
                cp_async16(sa, &A[(size_t)(mBase + row) * K + k0 + aCol0], v);
            }
#pragma unroll
            for (int p = 0; p < 2; p++) {
                int k = bK0 + p * 16;
                uint32_t sb = (uint32_t)__cvta_generic_to_shared(&Bs[nbuf][k][bN0]);
                cp_async16(sb, &B[(size_t)(k0 + k) * N + nBase + bN0], true);
            }
            cp_commit();
            cp_wait1();
        } else {
            cp_wait0();
        }
        __syncthreads();

#pragma unroll
        for (int kk = 0; kk < 32; kk += 16) {
            uint32_t a[4][4], b[4][2];
#pragma unroll
            for (int mi = 0; mi < 4; mi++) {
                uint32_t addr = (uint32_t)__cvta_generic_to_shared(
                    &As[buf][wm + mi * 16 + aRowOff][kk + aColOff]);
                asm volatile(
                    "ldmatrix.sync.aligned.m8n8.x4.shared.b16 {%0,%1,%2,%3}, [%4];\n"
                    : "=r"(a[mi][0]), "=r"(a[mi][1]), "=r"(a[mi][2]), "=r"(a[mi][3])
                    : "r"(addr));
            }
#pragma unroll
            for (int np = 0; np < 2; np++) {
                uint32_t addr = (uint32_t)__cvta_generic_to_shared(
                    &Bs[buf][kk + bRowOff][wn + np * 16 + bColOff]);
                asm volatile(
                    "ldmatrix.sync.aligned.m8n8.x4.trans.shared.b16 {%0,%1,%2,%3}, [%4];\n"
                    : "=r"(b[2 * np][0]), "=r"(b[2 * np][1]),
                      "=r"(b[2 * np + 1][0]), "=r"(b[2 * np + 1][1])
                    : "r"(addr));
            }
#pragma unroll
            for (int mi = 0; mi < 4; mi++)
#pragma unroll
                for (int ni = 0; ni < 4; ni++) {
                    asm volatile(
                        "mma.sync.aligned.m16n8k16.row.col.f32.f16.f16.f32 "
                        "{%0,%1,%2,%3}, {%4,%5,%6,%7}, {%8,%9}, {%0,%1,%2,%3};\n"
                        : "+f"(c[mi][ni][0]), "+f"(c[mi][ni][1]),
                          "+f"(c[mi][ni][2]), "+f"(c[mi][ni][3])
                        : "r"(a[mi][0]), "r"(a[mi][1]), "r"(a[mi][2]), "r"(a[mi][3]),
                          "r"(b[ni][0]), "r"(b[ni][1]));
                }
        }
        __syncthreads();
    }

    const int hh = nBase / HID;

    float* s_red = (float*)&As[0][0][0];

#pragma unroll
    for (int mi = 0; mi < 4; mi++) {
        int r0 = mBase + wm + mi * 16 + g;
        int r1 = r0 + 8;
        float ps0 = 0.f, pd0 = 0.f, ps1 = 0.f, pd1 = 0.f;
#pragma unroll
        for (int ni = 0; ni < 4; ni++) {
            int col = nBase + wn + ni * 8 + 2 * l;
            if (r0 < M)
                *(__half2*)&C[(size_t)r0 * N + col] =
                    __float22half2_rn(make_float2(c[mi][ni][0], c[mi][ni][1]));
            if (r1 < M)
                *(__half2*)&C[(size_t)r1 * N + col] =
                    __float22half2_rn(make_float2(c[mi][ni][2], c[mi][ni][3]));
            int cc = wn + ni * 8 + 2 * l;
            float sa0 = a_src[hh * HID + cc],     sa1 = a_src[hh * HID + cc + 1];
            float da0 = a_dst[hh * HID + cc],     da1 = a_dst[hh * HID + cc + 1];
            ps0 += c[mi][ni][0] * sa0 + c[mi][ni][1] * sa1;
            pd0 += c[mi][ni][0] * da0 + c[mi][ni][1] * da1;
            ps1 += c[mi][ni][2] * sa0 + c[mi][ni][3] * sa1;
            pd1 += c[mi][ni][2] * da0 + c[mi][ni][3] * da1;
        }
#pragma unroll
        for (int o = 1; o <= 2; o <<= 1) {
            ps0 += __shfl_xor_sync(0xffffffffu, ps0, o);
            pd0 += __shfl_xor_sync(0xffffffffu, pd0, o);
            ps1 += __shfl_xor_sync(0xffffffffu, ps1, o);
            pd1 += __shfl_xor_sync(0xffffffffu, pd1, o);
        }
        if (l == 0) {
            int lr0 = wm + mi * 16 + g;
            s_red[(lr0)     * 8 + wnIdx * 2 + 0] = ps0;
            s_red[(lr0)     * 8 + wnIdx * 2 + 1] = pd0;
            s_red[(lr0 + 8) * 8 + wnIdx * 2 + 0] = ps1;
            s_red[(lr0 + 8) * 8 + wnIdx * 2 + 1] = pd1;
        }
    }
    __syncthreads();
    if (tid < 128) {
        int gr = mBase + tid;
        if (gr < M) {
            float as = s_red[tid * 8 + 0] + s_red[tid * 8 + 2] +
                       s_red[tid * 8 + 4] + s_red[tid * 8 + 6];
            float ad = s_red[tid * 8 + 1] + s_red[tid * 8 + 3] +
                       s_red[tid * 8 + 5] + s_red[tid * 8 + 7];
            as_out[gr * H + hh] = as;
            ad_out[gr * H + hh] = ad;
        }
    }
}

// ==================== CSR build ====================
__global__ void deg_kernel(const int* __restrict__ dst, int* __restrict__ deg, int E)
{
    int e = blockIdx.x * blockDim.x + threadIdx.x;
    if (e < E) atomicAdd(&deg[dst[e]], 1);
}

// 8 items per thread, 1024 threads, single block
__global__ __launch_bounds__(1024) void scan_kernel(const int* __restrict__ deg,
                                                    int* __restrict__ rowstart, int n)
{
    __shared__ int warp_sums[32];
    __shared__ int s_carry;
    int t = threadIdx.x;
    int lane = t & 31, w = t >> 5;
    if (t == 0) s_carry = 0;
    __syncthreads();
    for (int base = 0; base < n; base += 8192) {
        int i0 = base + t * 8;
        int v[8];
        int s = 0;
#pragma unroll
        for (int q = 0; q < 8; q++) {
            v[q] = (i0 + q < n) ? deg[i0 + q] : 0;
            s += v[q];
        }
        int incl = s;
#pragma unroll
        for (int o = 1; o < 32; o <<= 1) {
            int y = __shfl_up_sync(0xffffffffu, incl, o);
            if (lane >= o) incl += y;
        }
        if (lane == 31) warp_sums[w] = incl;
        __syncthreads();
        if (w == 0) {
            int sw = warp_sums[lane];
#pragma unroll
            for (int o = 1; o < 32; o <<= 1) {
                int y = __shfl_up_sync(0xffffffffu, sw, o);
                if (lane >= o) sw += y;
            }
            warp_sums[lane] = sw;
        }
        __syncthreads();
        int run = s_carry + (w > 0 ? warp_sums[w - 1] : 0) + incl - s;
#pragma unroll
        for (int q = 0; q < 8; q++) {
            if (i0 + q < n) rowstart[i0 + q] = run;
            run += v[q];
        }
        __syncthreads();
        if (t == 0) s_carry += warp_sums[31];
        __syncthreads();
    }
    if (t == 0) rowstart[n] = s_carry;
}

__global__ void csr_scatter_kernel(const int* __restrict__ src, const int* __restrict__ dst,
                                   int* __restrict__ cursor, int* __restrict__ csr_src, int E)
{
    int e = blockIdx.x * blockDim.x + threadIdx.x;
    if (e >= E) return;
    int p = atomicAdd(&cursor[dst[e]], 1);
    csr_src[p] = src[e];
}

// ==================== FUSED aggregate, H=4: TWO warps per node (one per head pair) ====
__global__ __launch_bounds__(256) void gat_fused4_kernel(
    const int* __restrict__ rowstart, const int* __restrict__ csr_src,
    const float* __restrict__ as_, const float* __restrict__ ad_,
    const __half* __restrict__ hbuf, const float* __restrict__ bias,
    __half* __restrict__ out, int n)
{
    __shared__ int   s_src[8][32];
    __shared__ float s_cf[8][32][2];

    const int w = threadIdx.x >> 5;
    const int lane = threadIdx.x & 31;
    const int d = blockIdx.x * 4 + (w >> 1);
    const int hp = w & 1;
    if (d >= n) return;
    const int e0 = rowstart[d];
    const int deg = rowstart[d + 1] - e0;
    const int c0 = hp * 256 + lane * 8;
    const int hsel = lane >> 4;
    const float NEG_INF = -__int_as_float(0x7f800000);

    float2 advv = *(const float2*)&ad_[d * 4 + hp * 2];

    float acc[8];
#pragma unroll
    for (int i = 0; i < 8; i++) acc[i] = 0.f;

    if (deg <= 32) {
        bool valid = lane < deg;
        int s = 0;
        float v0, v1;
        if (valid) {
            s = __ldg(&csr_src[e0 + lane]);
            float2 av = __ldg((const float2*)&as_[s * 4 + hp * 2]);
            v0 = av.x + advv.x; v0 = (v0 >= 0.f) ? v0 : NEG_SLOPE * v0;
            v1 = av.y + advv.y; v1 = (v1 >= 0.f) ? v1 : NEG_SLOPE * v1;
        } else { v0 = NEG_INF; v1 = NEG_INF; }

        float mx0 = v0, mx1 = v1;
#pragma unroll
        for (int o = 16; o; o >>= 1) {
            mx0 = fmaxf(mx0, __shfl_xor_sync(0xffffffffu, mx0, o));
            mx1 = fmaxf(mx1, __shfl_xor_sync(0xffffffffu, mx1, o));
        }
        float e0f = valid ? expf(v0 - mx0) : 0.f;
        float e1f = valid ? expf(v1 - mx1) : 0.f;
        float sm0 = e0f, sm1 = e1f;
#pragma unroll
        for (int o = 16; o; o >>= 1) {
            sm0 += __shfl_xor_sync(0xffffffffu, sm0, o);
            sm1 += __shfl_xor_sync(0xffffffffu, sm1, o);
        }
        s_src[w][lane] = s;
        s_cf[w][lane][0] = e0f / (sm0 + 1e-16f);
        s_cf[w][lane][1] = e1f / (sm1 + 1e-16f);
        __syncwarp();

#pragma unroll 8
        for (int j = 0; j < deg; j++) {
            int sj = s_src[w][j];
            float cf = s_cf[w][j][hsel];
            uint4 r0 = __ldg((const uint4*)(hbuf + (size_t)sj * 512 + c0));
            const __half2* p0 = (const __half2*)&r0;
#pragma unroll
            for (int q = 0; q < 4; q++) {
                float2 f0 = __half22float2(p0[q]);
                acc[2 * q + 0] += f0.x * cf;
                acc[2 * q + 1] += f0.y * cf;
            }
        }
    } else {
        float mx0 = NEG_INF, mx1 = NEG_INF, sm0 = 0.f, sm1 = 0.f;
        for (int j = lane; j < deg; j += 32) {
            int s = __ldg(&csr_src[e0 + j]);
            float2 av = __ldg((const float2*)&as_[s * 4 + hp * 2]);
            float v0 = av.x + advv.x; v0 = (v0 >= 0.f) ? v0 : NEG_SLOPE * v0;
            float v1 = av.y + advv.y; v1 = (v1 >= 0.f) ? v1 : NEG_SLOPE * v1;
            mx0 = fmaxf(mx0, v0); mx1 = fmaxf(mx1, v1);
        }
#pragma unroll
        for (int o = 16; o; o >>= 1) {
            mx0 = fmaxf(mx0, __shfl_xor_sync(0xffffffffu, mx0, o));
            mx1 = fmaxf(mx1, __shfl_xor_sync(0xffffffffu, mx1, o));
        }
        for (int j = lane; j < deg; j += 32) {
            int s = __ldg(&csr_src[e0 + j]);
            float2 av = __ldg((const float2*)&as_[s * 4 + hp * 2]);
            float v0 = av.x + advv.x; v0 = (v0 >= 0.f) ? v0 : NEG_SLOPE * v0;
            float v1 = av.y + advv.y; v1 = (v1 >= 0.f) ? v1 : NEG_SLOPE * v1;
            sm0 += expf(v0 - mx0); sm1 += expf(v1 - mx1);
        }
#pragma unroll
        for (int o = 16; o; o >>= 1) {
            sm0 += __shfl_xor_sync(0xffffffffu, sm0, o);
            sm1 += __shfl_xor_sync(0xffffffffu, sm1, o);
        }
        float inv0 = 1.f / (sm0 + 1e-16f);
        float inv1 = 1.f / (sm1 + 1e-16f);

        for (int base = 0; base < deg; base += 32) {
            int j = base + lane;
            bool valid = j < deg;
            int s = 0;
            float cf0 = 0.f, cf1 = 0.f;
            if (valid) {
                s = __ldg(&csr_src[e0 + j]);
                float2 av = __ldg((const float2*)&as_[s * 4 + hp * 2]);
                float v0 = av.x + advv.x; v0 = (v0 >= 0.f) ? v0 : NEG_SLOPE * v0;
                float v1 = av.y + advv.y; v1 = (v1 >= 0.f) ? v1 : NEG_SLOPE * v1;
                cf0 = expf(v0 - mx0) * inv0;
                cf1 = expf(v1 - mx1) * inv1;
            }
            __syncwarp();
            s_src[w][lane] = s;
            s_cf[w][lane][0] = cf0;
            s_cf[w][lane][1] = cf1;
            __syncwarp();

            int nn = min(32, deg - base);
#pragma unroll 8
            for (int jj = 0; jj < nn; jj++) {
                int sj = s_src[w][jj];
                float cf = s_cf[w][jj][hsel];
                uint4 r0 = __ldg((const uint4*)(hbuf + (size_t)sj * 512 + c0));
                const __half2* p0 = (const __half2*)&r0;
#pragma unroll
                for (int q = 0; q < 4; q++) {
                    float2 f0 = __half22float2(p0[q]);
                    acc[2 * q + 0] += f0.x * cf;
                    acc[2 * q + 1] += f0.y * cf;
                }
            }
        }
    }

    float v[8];
#pragma unroll
    for (int i = 0; i < 8; i += 4) {
        float4 b = *(const float4*)&bias[c0 + i];
        v[i + 0] = acc[i + 0] + b.x;
        v[i + 1] = acc[i + 1] + b.y;
        v[i + 2] = acc[i + 2] + b.z;
        v[i + 3] = acc[i + 3] + b.w;
    }
#pragma unroll
    for (int i = 0; i < 8; i++) v[i] = (v[i] > 0.f) ? v[i] : expm1f(v[i]);
    __half2 hv[4];
#pragma unroll
    for (int i = 0; i < 4; i++)
        hv[i] = __float22half2_rn(make_float2(v[2 * i], v[2 * i + 1]));
    *(uint4*)&out[(size_t)d * 512 + c0] = *(uint4*)&hv[0];
}

// ==================== FUSED aggregate, H=1: warp per node, fp32 out, no ELU ====
__global__ __launch_bounds__(256) void gat_fused1_kernel(
    const int* __restrict__ rowstart, const int* __restrict__ csr_src,
    const float* __restrict__ as_, const float* __restrict__ ad_,
    const __half* __restrict__ hbuf, const float* __restrict__ bias,
    float* __restrict__ out, int n)
{
    __shared__ int   s_src[8][32];
    __shared__ float s_cf[8][32];

    const int w = threadIdx.x >> 5;
    const int lane = threadIdx.x & 31;
    const int d = blockIdx.x * 8 + w;
    if (d >= n) return;
    const int e0 = rowstart[d];
    const int deg = rowstart[d + 1] - e0;
    const int c0 = lane * 4;
    const float NEG_INF = -__int_as_float(0x7f800000);

    float adv = ad_[d];

    float acc[4] = {0.f, 0.f, 0.f, 0.f};

    if (deg <= 32) {
        bool valid = lane < deg;
        int s = 0;
        float v0;
        if (valid) {
            s = __ldg(&csr_src[e0 + lane]);
            v0 = __ldg(&as_[s]) + adv;
            v0 = (v0 >= 0.f) ? v0 : NEG_SLOPE * v0;
        } else v0 = NEG_INF;
        float mx = v0;
#pragma unroll
        for (int o = 16; o; o >>= 1)
            mx = fmaxf(mx, __shfl_xor_sync(0xffffffffu, mx, o));
        float e = valid ? expf(v0 - mx) : 0.f;
        float sm = e;
#pragma unroll
        for (int o = 16; o; o >>= 1)
            sm += __shfl_xor_sync(0xffffffffu, sm, o);
        s_src[w][lane] = s;
        s_cf[w][lane] = e / (sm + 1e-16f);
        __syncwarp();

#pragma unroll 8
        for (int j = 0; j < deg; j++) {
            int sj = s_src[w][j];
            float cf = s_cf[w][j];
            uint2 r0 = __ldg((const uint2*)(hbuf + (size_t)sj * HID + c0));
            const __half2* p0 = (const __half2*)&r0;
#pragma unroll
            for (int q = 0; q < 2; q++) {
                float2 f0 = __half22float2(p0[q]);
                acc[2 * q + 0] += f0.x * cf;
                acc[2 * q + 1] += f0.y * cf;
            }
        }
    } else {
        float mx = NEG_INF, sm = 0.f;
        for (int j = lane; j < deg; j += 32) {
            int s = __ldg(&csr_src[e0 + j]);
            float v = __ldg(&as_[s]) + adv;
            v = (v >= 0.f) ? v : NEG_SLOPE * v;
            mx = fmaxf(mx, v);
        }
#pragma unroll
        for (int o = 16; o; o >>= 1)
            mx = fmaxf(mx, __shfl_xor_sync(0xffffffffu, mx, o));
        for (int j = lane; j < deg; j += 32) {
            int s = __ldg(&csr_src[e0 + j]);
            float v = __ldg(&as_[s]) + adv;
            v = (v >= 0.f) ? v : NEG_SLOPE * v;
            sm += expf(v - mx);
        }
#pragma unroll
        for (int o = 16; o; o >>= 1)
            sm += __shfl_xor_sync(0xffffffffu, sm, o);
        float inv = 1.f / (sm + 1e-16f);

        for (int base = 0; base < deg; base += 32) {
            int j = base + lane;
            bool valid = j < deg;
            int s = 0;
            float cf = 0.f;
            if (valid) {
                s = __ldg(&csr_src[e0 + j]);
                float v = __ldg(&as_[s]) + adv;
                v = (v >= 0.f) ? v : NEG_SLOPE * v;
                cf = expf(v - mx) * inv;
            }
            __syncwarp();
            s_src[w][lane] = s;
            s_cf[w][lane] = cf;
            __syncwarp();

            int nn = min(32, deg - base);
#pragma unroll 8
            for (int jj = 0; jj < nn; jj++) {
                int sj = s_src[w][jj];
                float c = s_cf[w][jj];
                uint2 r0 = __ldg((const uint2*)(hbuf + (size_t)sj * HID + c0));
                const __half2* p0 = (const __half2*)&r0;
#pragma unroll
                for (int q = 0; q < 2; q++) {
                    float2 f0 = __half22float2(p0[q]);
                    acc[2 * q + 0] += f0.x * c;
                    acc[2 * q + 1] += f0.y * c;
                }
            }
        }
    }

    float4 b = *(const float4*)&bias[c0];
    *(float4*)&out[(size_t)d * HID + c0] =
        make_float4(acc[0] + b.x, acc[1] + b.y, acc[2] + b.z, acc[3] + b.w);
}

// ==================== pooling ====================
__global__ void pool_sum_kernel(const float* __restrict__ node_emb, const int* __restrict__ batch,
                                float* __restrict__ pool, float* __restrict__ cnt, int n)
{
    int node = blockIdx.x;
    int t = threadIdx.x;
    int g = batch[node];
    atomicAdd(&pool[g * HID + t], node_emb[(size_t)node * HID + t]);
    if (t == 0) atomicAdd(&cnt[g], 1.0f);
}

__global__ void pool_div_kernel(const float* __restrict__ pool, const float* __restrict__ cnt,
                                float* __restrict__ out)
{
    int i = blockIdx.x * blockDim.x + threadIdx.x;
    if (i >= NGRAPH * HID) return;
    int g = i / HID;
    out[i] = pool[i] / fmaxf(cnt[g], 1.0f);
}

// ==================== host side ====================
extern "C" void kernel_launch(void* const* d_in, const int* in_sizes, int n_in,
                              void* d_out, int out_size)
{
    const float* x     = (const float*)d_in[0];
    const int*   ei    = (const int*)d_in[1];
    const int*   batch = (const int*)d_in[2];
    const float* W1  = (const float*)d_in[3];
    const float* a1s = (const float*)d_in[4];
    const float* a1d = (const float*)d_in[5];
    const float* b1  = (const float*)d_in[6];
    const float* W2  = (const float*)d_in[7];
    const float* a2s = (const float*)d_in[8];
    const float* a2d = (const float*)d_in[9];
    const float* b2  = (const float*)d_in[10];
    const float* W3  = (const float*)d_in[11];
    const float* a3s = (const float*)d_in[12];
    const float* a3d = (const float*)d_in[13];
    const float* b3  = (const float*)d_in[14];

    const int n = in_sizes[0] / FIN;
    const int E = in_sizes[1] / 2;
    const int* src = ei;
    const int* dst = ei + E;

    float *alphab, *poolb, *cntb;
    __half *hbuf, *actH, *xH, *wH;
    int *degb, *rowstartb, *cursorb, *csrsrcb;
    cudaGetSymbolAddress((void**)&hbuf,      g_hh);
    cudaGetSymbolAddress((void**)&actH,      g_acth);
    cudaGetSymbolAddress((void**)&xH,        g_xh);
    cudaGetSymbolAddress((void**)&wH,        g_wh);
    cudaGetSymbolAddress((void**)&alphab,    g_alpha);
    cudaGetSymbolAddress((void**)&degb,      g_deg);
    cudaGetSymbolAddress((void**)&rowstartb, g_rowstart);
    cudaGetSymbolAddress((void**)&cursorb,   g_cursor);
    cudaGetSymbolAddress((void**)&csrsrcb,   g_csr_src);
    cudaGetSymbolAddress((void**)&poolb,     g_pool);
    cudaGetSymbolAddress((void**)&cntb,      g_cnt);

    __half* w1H = wH;
    __half* w2H = wH + FIN * HEADS * HID;
    __half* w3H = w2H + HEADS * HID * HEADS * HID;

    float* asb = alphab;
    float* adb = alphab + NN * HEADS;

    float* node_emb  = (float*)d_out;
    float* graph_emb = (float*)d_out + (size_t)n * HID;

    // k0: fused fp16 conversions
    int nx4 = n * FIN / 4;
    f2h_all_kernel<<<1184, 256>>>(x, W1, W2, W3, xH, w1H, w2H, w3H, nx4);

    // k1,k2: degree + scan
    cudaMemsetAsync(degb, 0, (size_t)n * sizeof(int));
    deg_kernel<<<(E + 255) / 256, 256>>>(dst, degb, E);
    scan_kernel<<<1, 1024>>>(degb, rowstartb, n);
    cudaMemcpyAsync(cursorb, rowstartb, (size_t)n * sizeof(int), cudaMemcpyDeviceToDevice);

    // k3: layer-1 GEMM (profiled slot — kernel index 3)
    {
        dim3 ggrid(4, (n + 127) / 128);
        h16_gemm_alpha_kernel<<<ggrid, 256>>>(xH, w1H, hbuf, n, FIN, 512,
                                              a1s, a1d, asb, adb, 4);
    }

    // k4: CSR scatter (needed only by the aggregate)
    csr_scatter_kernel<<<(E + 255) / 256, 256>>>(src, dst, cursorb, csrsrcb, E);

    // k5: layer-1 aggregate
    gat_fused4_kernel<<<(n + 3) / 4, 256>>>(rowstartb, csrsrcb, asb, adb,
                                            hbuf, b1, actH, n);
    // layer 2
    {
        dim3 ggrid(4, (n + 127) / 128);
        h16_gemm_alpha_kernel<<<ggrid, 256>>>(actH, w2H, hbuf, n, 512, 512,
                                              a2s, a2d, asb, adb, 4);
        gat_fused4_kernel<<<(n + 3) / 4, 256>>>(rowstartb, csrsrcb, asb, adb,
                                                hbuf, b2, actH, n);
    }
    // layer 3
    {
        dim3 ggrid(1, (n + 127) / 128);
        h16_gemm_alpha_kernel<<<ggrid, 256>>>(actH, w3H, hbuf, n, 512, 128,
                                              a3s, a3d, asb, adb, 1);
        gat_fused1_kernel<<<(n + 7) / 8, 256>>>(rowstartb, csrsrcb, asb, adb,
                                                hbuf, b3, node_emb, n);
    }

    // global mean pool
    cudaMemsetAsync(poolb, 0, NGRAPH * HID * sizeof(float));
    cudaMemsetAsync(cntb, 0, NGRAPH * sizeof(float));
    pool_sum_kernel<<<n, HID>>>(node_emb, batch, poolb, cntb, n);
    pool_div_kernel<<<(NGRAPH * HID + 127) / 128, 128>>>(poolb, cntb, graph_emb);
}

// round 16
// speedup vs baseline: 1.6501x; 1.0300x over previous
#include <cuda_runtime.h>
#include <cuda_fp16.h>
#include <cstdint>
#include <cstddef>

#define NN 50000
#define EE 800000
#define FIN 256
#define HID 128
#define HEADS 4
#define NGRAPH 50
#define NEG_SLOPE 0.2f

// GEMM smem layout (dynamic): As[2][128][72] halfs + Bs[2][64][136] halfs
#define AS_STRIDE 72
#define BS_STRIDE 136
#define AS_BUF_HALFS (128 * AS_STRIDE)          // 9216
#define BS_BUF_HALFS (64 * BS_STRIDE)           // 8704
#define GEMM_SMEM_BYTES (2 * AS_BUF_HALFS * 2 + 2 * BS_BUF_HALFS * 2)  // 71680

// ---------------- scratch (device globals; no allocation allowed) -------------
__device__ __half g_hh[(size_t)NN * HEADS * HID];    // GEMM output (fp16 messages)
__device__ __half g_acth[(size_t)NN * HEADS * HID];  // activations (fp16), layer input
__device__ __half g_xh[(size_t)NN * FIN];            // x converted to fp16
__device__ __half g_wh[512 * 512 + 256 * 512 + 512 * 128]; // fp16 weights
__device__ float g_alpha[2 * NN * HEADS];            // [0]=as, [NN*HEADS]=ad
__device__ int   g_deg[NN];
__device__ int   g_rowstart[NN + 1];
__device__ int   g_cursor[NN];
__device__ int   g_csr_src[EE];
__device__ float g_pool[NGRAPH * HID];
__device__ float g_cnt[NGRAPH];

// ==================== fused fp32 -> fp16 conversion (x + 3 weights) ============
__global__ void f2h_all_kernel(const float* __restrict__ x,
                               const float* __restrict__ w1,
                               const float* __restrict__ w2,
                               const float* __restrict__ w3,
                               __half* __restrict__ xH,
                               __half* __restrict__ w1H,
                               __half* __restrict__ w2H,
                               __half* __restrict__ w3H,
                               int nx4)
{
    const int t1 = FIN * HEADS * HID / 4;
    const int t2 = HEADS * HID * HEADS * HID / 4;
    const int t3 = HEADS * HID * HID / 4;
    int total = nx4 + t1 + t2 + t3;
    for (int i = blockIdx.x * blockDim.x + threadIdx.x; i < total;
         i += gridDim.x * blockDim.x) {
        const float* in; __half* out; int j;
        if (i < nx4)                { in = x;  out = xH;  j = i; }
        else if (i < nx4 + t1)      { in = w1; out = w1H; j = i - nx4; }
        else if (i < nx4 + t1 + t2) { in = w2; out = w2H; j = i - nx4 - t1; }
        else                        { in = w3; out = w3H; j = i - nx4 - t1 - t2; }
        float4 v = ((const float4*)in)[j];
        __half2 a = __float22half2_rn(make_float2(v.x, v.y));
        __half2 b = __float22half2_rn(make_float2(v.z, v.w));
        ((__half2*)out)[2 * j + 0] = a;
        ((__half2*)out)[2 * j + 1] = b;
    }
}

// ==================== cp.async helpers ====================
__device__ __forceinline__ void cp_async16(uint32_t smem_addr, const void* gptr, bool valid)
{
    int sz = valid ? 16 : 0;
    asm volatile("cp.async.cg.shared.global [%0], [%1], 16, %2;\n"
                 :: "r"(smem_addr), "l"(gptr), "r"(sz));
}
__device__ __forceinline__ void cp_commit() { asm volatile("cp.async.commit_group;\n"); }
__device__ __forceinline__ void cp_wait1()  { asm volatile("cp.async.wait_group 1;\n"); }
__device__ __forceinline__ void cp_wait0()  { asm volatile("cp.async.wait_group 0;\n"); }

// ==================== fp16 GEMM: BK=64, cp.async double-buffered, ldmatrix ====================
// C[M,N] = A[M,K] @ B[K,N]; fp32 accumulate. Block tile 128x128, BK=64,
// 256 threads = 8 warps (2m x 4n), warp tile 64x32. Fused alpha epilogue.
__global__ __launch_bounds__(256) void h16_gemm_alpha_kernel(
    const __half* __restrict__ A, const __half* __restrict__ B, __half* __restrict__ C,
    int M, int K, int N,
    const float* __restrict__ a_src, const float* __restrict__ a_dst,  // [H][HID]
    float* __restrict__ as_out, float* __restrict__ ad_out, int H)
{
    extern __shared__ __align__(16) char dynsmem[];
    __half* AsB = (__half*)dynsmem;                              // [2][128][72]
    __half* BsB = (__half*)(dynsmem + 2 * AS_BUF_HALFS * 2);     // [2][64][136]

    const int tid  = threadIdx.x;
    const int lane = tid & 31;
    const int warp = tid >> 5;
    const int wm = (warp & 1) * 64;
    const int wn = (warp >> 1) * 32;
    const int wnIdx = warp >> 1;

    const int mBase = blockIdx.y * 128;
    const int nBase = blockIdx.x * 128;

    float c[4][4][4];
#pragma unroll
    for (int mi = 0; mi < 4; mi++)
#pragma unroll
        for (int ni = 0; ni < 4; ni++)
#pragma unroll
            for (int q = 0; q < 4; q++) c[mi][ni][q] = 0.f;

    const int g = lane >> 2;
    const int l = lane & 3;

    // ldmatrix lane-address components
    const int aRowOff = lane & 15;
    const int aColOff = (lane >> 4) * 8;
    const int bRowOff = (lane & 7) + ((lane >> 3) & 1) * 8;
    const int bColOff = (lane >> 4) * 8;

    // tile-load thread mapping: 4 uint4 per thread for A and for B
    const int aRow0 = tid >> 3;               // 8 uint4 per 64-half row
    const int aCol0 = (tid & 7) * 8;
    const int bK0   = tid >> 4;               // 16 uint4 per 128-half k-row
    const int bN0   = (tid & 15) * 8;

    const int T = K >> 6;   // BK=64 tiles

    // ---- prologue: stage 0 ----
    {
#pragma unroll
        for (int p = 0; p < 4; p++) {
            int row = aRow0 + p * 32;
            bool v = (mBase + row) < M;
            uint32_t sa = (uint32_t)__cvta_generic_to_shared(
                AsB + (size_t)row * AS_STRIDE + aCol0);
            cp_async16(sa, &A[(size_t)(mBase + row) * K + aCol0], v);
        }
#pragma unroll
        for (int p = 0; p < 4; p++) {
            int k = bK0 + p * 16;
            uint32_t sb = (uint32_t)__cvta_generic_to_shared(
                BsB + (size_t)k * BS_STRIDE + bN0);
            cp_async16(sb, &B[(size_t)k * N + nBase + bN0], true);
        }
        cp_commit();
    }

    for (int t = 0; t < T; t++) {
        int buf = t & 1;
        __half* As = AsB + buf * AS_BUF_HALFS;
        __half* Bs = BsB + buf * BS_BUF_HALFS;
        if (t + 1 < T) {
            int k0 = (t + 1) << 6;
            int nbuf = buf ^ 1;
            __half* Asn = AsB + nbuf * AS_BUF_HALFS;
            __half* Bsn = BsB + nbuf * BS_BUF_HALFS;
#pragma unroll
            for (int p = 0; p < 4; p++) {
                int row = aRow0 + p * 32;
                bool v = (mBase + row) < M;
                uint32_t sa = (uint32_t)__cvta_generic_to_shared(
                    Asn + (size_t)row * AS_STRIDE + aCol0);
                cp_async16(sa, &A[(size_t)(mBase + row) * K + k0 + aCol0], v);
            }
#pragma unroll
            for (int p = 0; p < 4; p++) {
                int k = bK0 + p * 16;
                uint32_t sb = (uint32_t)__cvta_generic_to_shared(
                    Bsn + (size_t)k * BS_STRIDE + bN0);
                cp_async16(sb, &B[(size_t)(k0 + k) * N + nBase + bN0], true);
            }
            cp_commit();
            cp_wait1();
        } else {
            cp_wait0();
        }
        __syncthreads();

        // compute on buf: 4 k-steps of 16
#pragma unroll
        for (int kk = 0; kk < 64; kk += 16) {
            uint32_t a[4][4], b[4][2];
#pragma unroll
            for (int mi = 0; mi < 4; mi++) {
                uint32_t addr = (uint32_t)__cvta_generic_to_shared(
                    As + (size_t)(wm + mi * 16 + aRowOff) * AS_STRIDE + kk + aColOff);
                asm volatile(
                    "ldmatrix.sync.aligned.m8n8.x4.shared.b16 {%0,%1,%2,%3}, [%4];\n"
                    : "=r"(a[mi][0]), "=r"(a[mi][1]), "=r"(a[mi][2]), "=r"(a[mi][3])
                    : "r"(addr));
            }
#pragma unroll
            for (int np = 0; np < 2; np++) {
                uint32_t addr = (uint32_t)__cvta_generic_to_shared(
                    Bs + (size_t)(kk + bRowOff) * BS_STRIDE + wn + np * 16 + bColOff);
                asm volatile(
                    "ldmatrix.sync.aligned.m8n8.x4.trans.shared.b16 {%0,%1,%2,%3}, [%4];\n"
                    : "=r"(b[2 * np][0]), "=r"(b[2 * np][1]),
                      "=r"(b[2 * np + 1][0]), "=r"(b[2 * np + 1][1])
                    : "r"(addr));
            }
#pragma unroll
            for (int mi = 0; mi < 4; mi++)
#pragma unroll
                for (int ni = 0; ni < 4; ni++) {
                    asm volatile(
                        "mma.sync.aligned.m16n8k16.row.col.f32.f16.f16.f32 "
                        "{%0,%1,%2,%3}, {%4,%5,%6,%7}, {%8,%9}, {%0,%1,%2,%3};\n"
                        : "+f"(c[mi][ni][0]), "+f"(c[mi][ni][1]),
                          "+f"(c[mi][ni][2]), "+f"(c[mi][ni][3])
                        : "r"(a[mi][0]), "r"(a[mi][1]), "r"(a[mi][2]), "r"(a[mi][3]),
                          "r"(b[ni][0]), "r"(b[ni][1]));
                }
        }
        __syncthreads();
    }

    const int hh = nBase / HID;

    float* s_red = (float*)dynsmem;   // 128*8 floats

#pragma unroll
    for (int mi = 0; mi < 4; mi++) {
        int r0 = mBase + wm + mi * 16 + g;
        int r1 = r0 + 8;
        float ps0 = 0.f, pd0 = 0.f, ps1 = 0.f, pd1 = 0.f;
#pragma unroll
        for (int ni = 0; ni < 4; ni++) {
            int col = nBase + wn + ni * 8 + 2 * l;
            if (r0 < M)
                *(__half2*)&C[(size_t)r0 * N + col] =
                    __float22half2_rn(make_float2(c[mi][ni][0], c[mi][ni][1]));
            if (r1 < M)
                *(__half2*)&C[(size_t)r1 * N + col] =
                    __float22half2_rn(make_float2(c[mi][ni][2], c[mi][ni][3]));
            int cc = wn + ni * 8 + 2 * l;
            float sa0 = a_src[hh * HID + cc],     sa1 = a_src[hh * HID + cc + 1];
            float da0 = a_dst[hh * HID + cc],     da1 = a_dst[hh * HID + cc + 1];
            ps0 += c[mi][ni][0] * sa0 + c[mi][ni][1] * sa1;
            pd0 += c[mi][ni][0] * da0 + c[mi][ni][1] * da1;
            ps1 += c[mi][ni][2] * sa0 + c[mi][ni][3] * sa1;
            pd1 += c[mi][ni][2] * da0 + c[mi][ni][3] * da1;
        }
#pragma unroll
        for (int o = 1; o <= 2; o <<= 1) {
            ps0 += __shfl_xor_sync(0xffffffffu, ps0, o);
            pd0 += __shfl_xor_sync(0xffffffffu, pd0, o);
            ps1 += __shfl_xor_sync(0xffffffffu, ps1, o);
            pd1 += __shfl_xor_sync(0xffffffffu, pd1, o);
        }
        if (l == 0) {
            int lr0 = wm + mi * 16 + g;
            s_red[(lr0)     * 8 + wnIdx * 2 + 0] = ps0;
            s_red[(lr0)     * 8 + wnIdx * 2 + 1] = pd0;
            s_red[(lr0 + 8) * 8 + wnIdx * 2 + 0] = ps1;
            s_red[(lr0 + 8) * 8 + wnIdx * 2 + 1] = pd1;
        }
    }
    __syncthreads();
    if (tid < 128) {
        int gr = mBase + tid;
        if (gr < M) {
            float as = s_red[tid * 8 + 0] + s_red[tid * 8 + 2] +
                       s_red[tid * 8 + 4] + s_red[tid * 8 + 6];
            float ad = s_red[tid * 8 + 1] + s_red[tid * 8 + 3] +
                       s_red[tid * 8 + 5] + s_red[tid * 8 + 7];
            as_out[gr * H + hh] = as;
            ad_out[gr * H + hh] = ad;
        }
    }
}

// ==================== CSR build ====================
__global__ void deg_kernel(const int* __restrict__ dst, int* __restrict__ deg, int E)
{
    int e = blockIdx.x * blockDim.x + threadIdx.x;
    if (e < E) atomicAdd(&deg[dst[e]], 1);
}

__global__ __launch_bounds__(1024) void scan_kernel(const int* __restrict__ deg,
                                                    int* __restrict__ rowstart, int n)
{
    __shared__ int warp_sums[32];
    __shared__ int s_carry;
    int t = threadIdx.x;
    int lane = t & 31, w = t >> 5;
    if (t == 0) s_carry = 0;
    __syncthreads();
    for (int base = 0; base < n; base += 8192) {
        int i0 = base + t * 8;
        int v[8];
        int s = 0;
#pragma unroll
        for (int q = 0; q < 8; q++) {
            v[q] = (i0 + q < n) ? deg[i0 + q] : 0;
            s += v[q];
        }
        int incl = s;
#pragma unroll
        for (int o = 1; o < 32; o <<= 1) {
            int y = __shfl_up_sync(0xffffffffu, incl, o);
            if (lane >= o) incl += y;
        }
        if (lane == 31) warp_sums[w] = incl;
        __syncthreads();
        if (w == 0) {
            int sw = warp_sums[lane];
#pragma unroll
            for (int o = 1; o < 32; o <<= 1) {
                int y = __shfl_up_sync(0xffffffffu, sw, o);
                if (lane >= o) sw += y;
            }
            warp_sums[lane] = sw;
        }
        __syncthreads();
        int run = s_carry + (w > 0 ? warp_sums[w - 1] : 0) + incl - s;
#pragma unroll
        for (int q = 0; q < 8; q++) {
            if (i0 + q < n) rowstart[i0 + q] = run;
            run += v[q];
        }
        __syncthreads();
        if (t == 0) s_carry += warp_sums[31];
        __syncthreads();
    }
    if (t == 0) rowstart[n] = s_carry;
}

__global__ void csr_scatter_kernel(const int* __restrict__ src, const int* __restrict__ dst,
                                   int* __restrict__ cursor, int* __restrict__ csr_src, int E)
{
    int e = blockIdx.x * blockDim.x + threadIdx.x;
    if (e >= E) return;
    int p = atomicAdd(&cursor[dst[e]], 1);
    csr_src[p] = src[e];
}

// ==================== FUSED aggregate, H=4: TWO warps per node (one per head pair) ====
__global__ __launch_bounds__(256) void gat_fused4_kernel(
    const int* __restrict__ rowstart, const int* __restrict__ csr_src,
    const float* __restrict__ as_, const float* __restrict__ ad_,
    const __half* __restrict__ hbuf, const float* __restrict__ bias,
    __half* __restrict__ out, int n)
{
    __shared__ int   s_src[8][32];
    __shared__ float s_cf[8][32][2];

    const int w = threadIdx.x >> 5;
    const int lane = threadIdx.x & 31;
    const int d = blockIdx.x * 4 + (w >> 1);
    const int hp = w & 1;
    if (d >= n) return;
    const int e0 = rowstart[d];
    const int deg = rowstart[d + 1] - e0;
    const int c0 = hp * 256 + lane * 8;
    const int hsel = lane >> 4;
    const float NEG_INF = -__int_as_float(0x7f800000);

    float2 advv = *(const float2*)&ad_[d * 4 + hp * 2];

    float acc[8];
#pragma unroll
    for (int i = 0; i < 8; i++) acc[i] = 0.f;

    if (deg <= 32) {
        bool valid = lane < deg;
        int s = 0;
        float v0, v1;
        if (valid) {
            s = __ldg(&csr_src[e0 + lane]);
            float2 av = __ldg((const float2*)&as_[s * 4 + hp * 2]);
            v0 = av.x + advv.x; v0 = (v0 >= 0.f) ? v0 : NEG_SLOPE * v0;
            v1 = av.y + advv.y; v1 = (v1 >= 0.f) ? v1 : NEG_SLOPE * v1;
        } else { v0 = NEG_INF; v1 = NEG_INF; }

        float mx0 = v0, mx1 = v1;
#pragma unroll
        for (int o = 16; o; o >>= 1) {
            mx0 = fmaxf(mx0, __shfl_xor_sync(0xffffffffu, mx0, o));
            mx1 = fmaxf(mx1, __shfl_xor_sync(0xffffffffu, mx1, o));
        }
        float e0f = valid ? expf(v0 - mx0) : 0.f;
        float e1f = valid ? expf(v1 - mx1) : 0.f;
        float sm0 = e0f, sm1 = e1f;
#pragma unroll
        for (int o = 16; o; o >>= 1) {
            sm0 += __shfl_xor_sync(0xffffffffu, sm0, o);
            sm1 += __shfl_xor_sync(0xffffffffu, sm1, o);
        }
        s_src[w][lane] = s;
        s_cf[w][lane][0] = e0f / (sm0 + 1e-16f);
        s_cf[w][lane][1] = e1f / (sm1 + 1e-16f);
        __syncwarp();

#pragma unroll 8
        for (int j = 0; j < deg; j++) {
            int sj = s_src[w][j];
            float cf = s_cf[w][j][hsel];
            uint4 r0 = __ldg((const uint4*)(hbuf + (size_t)sj * 512 + c0));
            const __half2* p0 = (const __half2*)&r0;
#pragma unroll
            for (int q = 0; q < 4; q++) {
                float2 f0 = __half22float2(p0[q]);
                acc[2 * q + 0] += f0.x * cf;
                acc[2 * q + 1] += f0.y * cf;
            }
        }
    } else {
        float mx0 = NEG_INF, mx1 = NEG_INF, sm0 = 0.f, sm1 = 0.f;
        for (int j = lane; j < deg; j += 32) {
            int s = __ldg(&csr_src[e0 + j]);
            float2 av = __ldg((const float2*)&as_[s * 4 + hp * 2]);
            float v0 = av.x + advv.x; v0 = (v0 >= 0.f) ? v0 : NEG_SLOPE * v0;
            float v1 = av.y + advv.y; v1 = (v1 >= 0.f) ? v1 : NEG_SLOPE * v1;
            mx0 = fmaxf(mx0, v0); mx1 = fmaxf(mx1, v1);
        }
#pragma unroll
        for (int o = 16; o; o >>= 1) {
            mx0 = fmaxf(mx0, __shfl_xor_sync(0xffffffffu, mx0, o));
            mx1 = fmaxf(mx1, __shfl_xor_sync(0xffffffffu, mx1, o));
        }
        for (int j = lane; j < deg; j += 32) {
            int s = __ldg(&csr_src[e0 + j]);
            float2 av = __ldg((const float2*)&as_[s * 4 + hp * 2]);
            float v0 = av.x + advv.x; v0 = (v0 >= 0.f) ? v0 : NEG_SLOPE * v0;
            float v1 = av.y + advv.y; v1 = (v1 >= 0.f) ? v1 : NEG_SLOPE * v1;
            sm0 += expf(v0 - mx0); sm1 += expf(v1 - mx1);
        }
#pragma unroll
        for (int o = 16; o; o >>= 1) {
            sm0 += __shfl_xor_sync(0xffffffffu, sm0, o);
            sm1 += __shfl_xor_sync(0xffffffffu, sm1, o);
        }
        float inv0 = 1.f / (sm0 + 1e-16f);
        float inv1 = 1.f / (sm1 + 1e-16f);

        for (int base = 0; base < deg; base += 32) {
            int j = base + lane;
            bool valid = j < deg;
            int s = 0;
            float cf0 = 0.f, cf1 = 0.f;
            if (valid) {
                s = __ldg(&csr_src[e0 + j]);
                float2 av = __ldg((const float2*)&as_[s * 4 + hp * 2]);
                float v0 = av.x + advv.x; v0 = (v0 >= 0.f) ? v0 : NEG_SLOPE * v0;
                float v1 = av.y + advv.y; v1 = (v1 >= 0.f) ? v1 : NEG_SLOPE * v1;
                cf0 = expf(v0 - mx0) * inv0;
                cf1 = expf(v1 - mx1) * inv1;
            }
            __syncwarp();
            s_src[w][lane] = s;
            s_cf[w][lane][0] = cf0;
            s_cf[w][lane][1] = cf1;
            __syncwarp();

            int nn = min(32, deg - base);
#pragma unroll 8
            for (int jj = 0; jj < nn; jj++) {
                int sj = s_src[w][jj];
                float cf = s_cf[w][jj][hsel];
                uint4 r0 = __ldg((const uint4*)(hbuf + (size_t)sj * 512 + c0));
                const __half2* p0 = (const __half2*)&r0;
#pragma unroll
                for (int q = 0; q < 4; q++) {
                    float2 f0 = __half22float2(p0[q]);
                    acc[2 * q + 0] += f0.x * cf;
                    acc[2 * q + 1] += f0.y * cf;
                }
            }
        }
    }

    float v[8];
#pragma unroll
    for (int i = 0; i < 8; i += 4) {
        float4 b = *(const float4*)&bias[c0 + i];
        v[i + 0] = acc[i + 0] + b.x;
        v[i + 1] = acc[i + 1] + b.y;
        v[i + 2] = acc[i + 2] + b.z;
        v[i + 3] = acc[i + 3] + b.w;
    }
#pragma unroll
    for (int i = 0; i < 8; i++) v[i] = (v[i] > 0.f) ? v[i] : expm1f(v[i]);
    __half2 hv[4];
#pragma unroll
    for (int i = 0; i < 4; i++)
        hv[i] = __float22half2_rn(make_float2(v[2 * i], v[2 * i + 1]));
    *(uint4*)&out[(size_t)d * 512 + c0] = *(uint4*)&hv[0];
}

// ==================== FUSED aggregate, H=1: warp per node, fp32 out, no ELU ====
__global__ __launch_bounds__(256) void gat_fused1_kernel(
    const int* __restrict__ rowstart, const int* __restrict__ csr_src,
    const float* __restrict__ as_, const float* __restrict__ ad_,
    const __half* __restrict__ hbuf, const float* __restrict__ bias,
    float* __restrict__ out, int n)
{
    __shared__ int   s_src[8][32];
    __shared__ float s_cf[8][32];

    const int w = threadIdx.x >> 5;
    const int lane = threadIdx.x & 31;
    const int d = blockIdx.x * 8 + w;
    if (d >= n) return;
    const int e0 = rowstart[d];
    const int deg = rowstart[d + 1] - e0;
    const int c0 = lane * 4;
    const float NEG_INF = -__int_as_float(0x7f800000);

    float adv = ad_[d];

    float acc[4] = {0.f, 0.f, 0.f, 0.f};

    if (deg <= 32) {
        bool valid = lane < deg;
        int s = 0;
        float v0;
        if (valid) {
            s = __ldg(&csr_src[e0 + lane]);
            v0 = __ldg(&as_[s]) + adv;
            v0 = (v0 >= 0.f) ? v0 : NEG_SLOPE * v0;
        } else v0 = NEG_INF;
        float mx = v0;
#pragma unroll
        for (int o = 16; o; o >>= 1)
            mx = fmaxf(mx, __shfl_xor_sync(0xffffffffu, mx, o));
        float e = valid ? expf(v0 - mx) : 0.f;
        float sm = e;
#pragma unroll
        for (int o = 16; o; o >>= 1)
            sm += __shfl_xor_sync(0xffffffffu, sm, o);
        s_src[w][lane] = s;
        s_cf[w][lane] = e / (sm + 1e-16f);
        __syncwarp();

#pragma unroll 8
        for (int j = 0; j < deg; j++) {
            int sj = s_src[w][j];
            float cf = s_cf[w][j];
            uint2 r0 = __ldg((const uint2*)(hbuf + (size_t)sj * HID + c0));
            const __half2* p0 = (const __half2*)&r0;
#pragma unroll
            for (int q = 0; q < 2; q++) {
                float2 f0 = __half22float2(p0[q]);
                acc[2 * q + 0] += f0.x * cf;
                acc[2 * q + 1] += f0.y * cf;
            }
        }
    } else {
        float mx = NEG_INF, sm = 0.f;
        for (int j = lane; j < deg; j += 32) {
            int s = __ldg(&csr_src[e0 + j]);
            float v = __ldg(&as_[s]) + adv;
            v = (v >= 0.f) ? v : NEG_SLOPE * v;
            mx = fmaxf(mx, v);
        }
#pragma unroll
        for (int o = 16; o; o >>= 1)
            mx = fmaxf(mx, __shfl_xor_sync(0xffffffffu, mx, o));
        for (int j = lane; j < deg; j += 32) {
            int s = __ldg(&csr_src[e0 + j]);
            float v = __ldg(&as_[s]) + adv;
            v = (v >= 0.f) ? v : NEG_SLOPE * v;
            sm += expf(v - mx);
        }
#pragma unroll
        for (int o = 16; o; o >>= 1)
            sm += __shfl_xor_sync(0xffffffffu, sm, o);
        float inv = 1.f / (sm + 1e-16f);

        for (int base = 0; base < deg; base += 32) {
            int j = base + lane;
            bool valid = j < deg;
            int s = 0;
            float cf = 0.f;
            if (valid) {
                s = __ldg(&csr_src[e0 + j]);
                float v = __ldg(&as_[s]) + adv;
                v = (v >= 0.f) ? v : NEG_SLOPE * v;
                cf = expf(v - mx) * inv;
            }
            __syncwarp();
            s_src[w][lane] = s;
            s_cf[w][lane] = cf;
            __syncwarp();

            int nn = min(32, deg - base);
#pragma unroll 8
            for (int jj = 0; jj < nn; jj++) {
                int sj = s_src[w][jj];
                float c = s_cf[w][jj];
                uint2 r0 = __ldg((const uint2*)(hbuf + (size_t)sj * HID + c0));
                const __half2* p0 = (const __half2*)&r0;
#pragma unroll
                for (int q = 0; q < 2; q++) {
                    float2 f0 = __half22float2(p0[q]);
                    acc[2 * q + 0] += f0.x * c;
                    acc[2 * q + 1] += f0.y * c;
                }
            }
        }
    }

    float4 b = *(const float4*)&bias[c0];
    *(float4*)&out[(size_t)d * HID + c0] =
        make_float4(acc[0] + b.x, acc[1] + b.y, acc[2] + b.z, acc[3] + b.w);
}

// ==================== pooling ====================
__global__ void pool_sum_kernel(const float* __restrict__ node_emb, const int* __restrict__ batch,
                                float* __restrict__ pool, float* __restrict__ cnt, int n)
{
    int node = blockIdx.x;
    int t = threadIdx.x;
    int g = batch[node];
    atomicAdd(&pool[g * HID + t], node_emb[(size_t)node * HID + t]);
    if (t == 0) atomicAdd(&cnt[g], 1.0f);
}

__global__ void pool_div_kernel(const float* __restrict__ pool, const float* __restrict__ cnt,
                                float* __restrict__ out)
{
    int i = blockIdx.x * blockDim.x + threadIdx.x;
    if (i >= NGRAPH * HID) return;
    int g = i / HID;
    out[i] = pool[i] / fmaxf(cnt[g], 1.0f);
}

// ==================== host side ====================
extern "C" void kernel_launch(void* const* d_in, const int* in_sizes, int n_in,
                              void* d_out, int out_size)
{
    const float* x     = (const float*)d_in[0];
    const int*   ei    = (const int*)d_in[1];
    const int*   batch = (const int*)d_in[2];
    const float* W1  = (const float*)d_in[3];
    const float* a1s = (const float*)d_in[4];
    const float* a1d = (const float*)d_in[5];
    const float* b1  = (const float*)d_in[6];
    const float* W2  = (const float*)d_in[7];
    const float* a2s = (const float*)d_in[8];
    const float* a2d = (const float*)d_in[9];
    const float* b2  = (const float*)d_in[10];
    const float* W3  = (const float*)d_in[11];
    const float* a3s = (const float*)d_in[12];
    const float* a3d = (const float*)d_in[13];
    const float* b3  = (const float*)d_in[14];

    const int n = in_sizes[0] / FIN;
    const int E = in_sizes[1] / 2;
    const int* src = ei;
    const int* dst = ei + E;

    float *alphab, *poolb, *cntb;
    __half *hbuf, *actH, *xH, *wH;
    int *degb, *rowstartb, *cursorb, *csrsrcb;
    cudaGetSymbolAddress((void**)&hbuf,      g_hh);
    cudaGetSymbolAddress((void**)&actH,      g_acth);
    cudaGetSymbolAddress((void**)&xH,        g_xh);
    cudaGetSymbolAddress((void**)&wH,        g_wh);
    cudaGetSymbolAddress((void**)&alphab,    g_alpha);
    cudaGetSymbolAddress((void**)&degb,      g_deg);
    cudaGetSymbolAddress((void**)&rowstartb, g_rowstart);
    cudaGetSymbolAddress((void**)&cursorb,   g_cursor);
    cudaGetSymbolAddress((void**)&csrsrcb,   g_csr_src);
    cudaGetSymbolAddress((void**)&poolb,     g_pool);
    cudaGetSymbolAddress((void**)&cntb,      g_cnt);

    __half* w1H = wH;
    __half* w2H = wH + FIN * HEADS * HID;
    __half* w3H = w2H + HEADS * HID * HEADS * HID;

    float* asb = alphab;
    float* adb = alphab + NN * HEADS;

    float* node_emb  = (float*)d_out;
    float* graph_emb = (float*)d_out + (size_t)n * HID;

    // allow 70KB dynamic smem for the GEMM (executes at capture time; not captured)
    cudaFuncSetAttribute(h16_gemm_alpha_kernel,
                         cudaFuncAttributeMaxDynamicSharedMemorySize, GEMM_SMEM_BYTES);

    // k0: fused fp16 conversions
    int nx4 = n * FIN / 4;
    f2h_all_kernel<<<1184, 256>>>(x, W1, W2, W3, xH, w1H, w2H, w3H, nx4);

    // k1,k2: degree + scan
    cudaMemsetAsync(degb, 0, (size_t)n * sizeof(int));
    deg_kernel<<<(E + 255) / 256, 256>>>(dst, degb, E);
    scan_kernel<<<1, 1024>>>(degb, rowstartb, n);
    cudaMemcpyAsync(cursorb, rowstartb, (size_t)n * sizeof(int), cudaMemcpyDeviceToDevice);

    // k3: layer-1 GEMM (profiled slot — kernel index 3)
    {
        dim3 ggrid(4, (n + 127) / 128);
        h16_gemm_alpha_kernel<<<ggrid, 256, GEMM_SMEM_BYTES>>>(
            xH, w1H, hbuf, n, FIN, 512, a1s, a1d, asb, adb, 4);
    }

    // k4: CSR scatter
    csr_scatter_kernel<<<(E + 255) / 256, 256>>>(src, dst, cursorb, csrsrcb, E);

    // k5: layer-1 aggregate
    gat_fused4_kernel<<<(n + 3) / 4, 256>>>(rowstartb, csrsrcb, asb, adb,
                                            hbuf, b1, actH, n);
    // layer 2
    {
        dim3 ggrid(4, (n + 127) / 128);
        h16_gemm_alpha_kernel<<<ggrid, 256, GEMM_SMEM_BYTES>>>(
            actH, w2H, hbuf, n, 512, 512, a2s, a2d, asb, adb, 4);
        gat_fused4_kernel<<<(n + 3) / 4, 256>>>(rowstartb, csrsrcb, asb, adb,
                                                hbuf, b2, actH, n);
    }
    // layer 3
    {
        dim3 ggrid(1, (n + 127) / 128);
        h16_gemm_alpha_kernel<<<ggrid, 256, GEMM_SMEM_BYTES>>>(
            actH, w3H, hbuf, n, 512, 128, a3s, a3d, asb, adb, 1);
        gat_fused1_kernel<<<(n + 7) / 8, 256>>>(rowstartb, csrsrcb, asb, adb,
                                                hbuf, b3, node_emb, n);
    }

    // global mean pool
    cudaMemsetAsync(poolb, 0, NGRAPH * HID * sizeof(float));
    cudaMemsetAsync(cntb, 0, NGRAPH * sizeof(float));
    pool_sum_kernel<<<n, HID>>>(node_emb, batch, poolb, cntb, n);
    pool_div_kernel<<<(NGRAPH * HID + 127) / 128, 128>>>(poolb, cntb, graph_emb);
}